// round 1
// baseline (speedup 1.0000x reference)
#include <cuda_runtime.h>
#include <cuda_bf16.h>
#include <math.h>

#define NG 2048
#define IMW 128
#define IMH 128
#define FX 400.0f
#define FY 400.0f
#define CX 64.0f
#define CY 64.0f

// packed per-gaussian record: ux, uy, cinv0, cinv1 | cinv2, alpha, col_r, col_g | col_b, pad, pad, pad
__device__ float  g_packed[NG * 12];
__device__ float  g_depth[NG];
__device__ float4 g_sorted[NG * 3];

__constant__ float kSH_C0 = 0.28209479177387814f;
__constant__ float kSH_C1 = 0.4886025119029199f;

__global__ void preprocess_kernel(const float* __restrict__ pws,
                                  const float* __restrict__ shs,
                                  const float* __restrict__ alphas_raw,
                                  const float* __restrict__ scales_raw,
                                  const float* __restrict__ rots_raw,
                                  const float* __restrict__ Rcw,
                                  const float* __restrict__ tcw,
                                  float* __restrict__ areas_out)
{
    int i = blockIdx.x * blockDim.x + threadIdx.x;
    if (i >= NG) return;

    // camera
    float R00 = Rcw[0], R01 = Rcw[1], R02 = Rcw[2];
    float R10 = Rcw[3], R11 = Rcw[4], R12 = Rcw[5];
    float R20 = Rcw[6], R21 = Rcw[7], R22 = Rcw[8];
    float t0 = tcw[0], t1 = tcw[1], t2 = tcw[2];

    float pwx = pws[i*3+0], pwy = pws[i*3+1], pwz = pws[i*3+2];

    // pcs = Rcw @ pw + tcw
    float pc0 = R00*pwx + R01*pwy + R02*pwz + t0;
    float pc1 = R10*pwx + R11*pwy + R12*pwz + t1;
    float pc2 = R20*pwx + R21*pwy + R22*pwz + t2;

    float depth = pc2;
    bool valid = depth > 0.2f;
    float z = valid ? depth : 1.0f;

    float ux = FX * pc0 / z + CX;
    float uy = FY * pc1 / z + CY;

    // quaternion -> rotation
    float qw = rots_raw[i*4+0], qx = rots_raw[i*4+1], qy = rots_raw[i*4+2], qz = rots_raw[i*4+3];
    float qn = rsqrtf(qw*qw + qx*qx + qy*qy + qz*qz);
    qw *= qn; qx *= qn; qy *= qn; qz *= qn;

    float r00 = 1.0f - 2.0f*(qy*qy + qz*qz);
    float r01 = 2.0f*(qx*qy - qw*qz);
    float r02 = 2.0f*(qx*qz + qw*qy);
    float r10 = 2.0f*(qx*qy + qw*qz);
    float r11 = 1.0f - 2.0f*(qx*qx + qz*qz);
    float r12 = 2.0f*(qy*qz - qw*qx);
    float r20 = 2.0f*(qx*qz - qw*qy);
    float r21 = 2.0f*(qy*qz + qw*qx);
    float r22 = 1.0f - 2.0f*(qx*qx + qy*qy);

    float s0 = expf(scales_raw[i*3+0]);
    float s1 = expf(scales_raw[i*3+1]);
    float s2 = expf(scales_raw[i*3+2]);

    // M = R * diag-ish (column scaling), cov3d = M M^T (symmetric)
    float m00 = r00*s0, m01 = r01*s1, m02 = r02*s2;
    float m10 = r10*s0, m11 = r11*s1, m12 = r12*s2;
    float m20 = r20*s0, m21 = r21*s1, m22 = r22*s2;

    float Sxx = m00*m00 + m01*m01 + m02*m02;
    float Sxy = m00*m10 + m01*m11 + m02*m12;
    float Sxz = m00*m20 + m01*m21 + m02*m22;
    float Syy = m10*m10 + m11*m11 + m12*m12;
    float Syz = m10*m20 + m11*m21 + m12*m22;
    float Szz = m20*m20 + m21*m21 + m22*m22;

    const float limx = 1.3f * 0.5f * (float)IMW / FX;
    const float limy = 1.3f * 0.5f * (float)IMH / FY;
    float tx = fminf(fmaxf(pc0 / z, -limx), limx) * z;
    float ty = fminf(fmaxf(pc1 / z, -limy), limy) * z;

    float j00 = FX / z;
    float j02 = -FX * tx / (z*z);
    float j11 = FY / z;
    float j12 = -FY * ty / (z*z);

    // T = J @ Rcw (2x3)
    float T00 = j00*R00 + j02*R20;
    float T01 = j00*R01 + j02*R21;
    float T02 = j00*R02 + j02*R22;
    float T10 = j11*R10 + j12*R20;
    float T11 = j11*R11 + j12*R21;
    float T12 = j11*R12 + j12*R22;

    // cov2d = T cov3d T^T + 0.3 I
    float u0 = T00*Sxx + T01*Sxy + T02*Sxz;
    float u1 = T00*Sxy + T01*Syy + T02*Syz;
    float u2 = T00*Sxz + T01*Syz + T02*Szz;
    float v0 = T10*Sxx + T11*Sxy + T12*Sxz;
    float v1 = T10*Sxy + T11*Syy + T12*Syz;
    float v2 = T10*Sxz + T11*Syz + T12*Szz;

    float a = u0*T00 + u1*T01 + u2*T02 + 0.3f;
    float b = u0*T10 + u1*T11 + u2*T12;
    float c = v0*T10 + v1*T11 + v2*T12 + 0.3f;

    float det = a*c - b*b;
    valid = valid && (det > 0.0f);
    float det_s = valid ? det : 1.0f;
    float ci0 = c / det_s;
    float ci1 = -b / det_s;
    float ci2 = a / det_s;

    float mid = 0.5f * (a + c);
    float disc = sqrtf(fmaxf(mid*mid - det, 0.1f));
    float ar0 = 3.0f * sqrtf(fmaxf(mid + disc, 0.0f));
    float ar1 = 3.0f * sqrtf(fmaxf(mid - disc, 0.0f));
    areas_out[2*i+0] = valid ? ar0 : 0.0f;
    areas_out[2*i+1] = valid ? ar1 : 0.0f;

    // dirs = normalize(pw - twc), twc = -Rcw^T tcw
    float twc0 = -(R00*t0 + R10*t1 + R20*t2);
    float twc1 = -(R01*t0 + R11*t1 + R21*t2);
    float twc2 = -(R02*t0 + R12*t1 + R22*t2);
    float dx = pwx - twc0, dy = pwy - twc1, dz = pwz - twc2;
    float dn = rsqrtf(dx*dx + dy*dy + dz*dz);
    float x = dx*dn, y = dy*dn, zd = dz*dn;

    float xx = x*x, yy = y*y, zz = zd*zd;
    float xy = x*y, yz = y*zd, xz = x*zd;

    // SH basis
    float bs[16];
    bs[0]  = kSH_C0;
    bs[1]  = -kSH_C1 * y;
    bs[2]  =  kSH_C1 * zd;
    bs[3]  = -kSH_C1 * x;
    bs[4]  =  1.0925484305920792f  * xy;
    bs[5]  = -1.0925484305920792f  * yz;
    bs[6]  =  0.31539156525252005f * (2.0f*zz - xx - yy);
    bs[7]  = -1.0925484305920792f  * xz;
    bs[8]  =  0.5462742152960396f  * (xx - yy);
    bs[9]  = -0.5900435899266435f  * y * (3.0f*xx - yy);
    bs[10] =  2.890611442640554f   * xy * zd;
    bs[11] = -0.4570457994644658f  * y * (4.0f*zz - xx - yy);
    bs[12] =  0.3731763325901154f  * zd * (2.0f*zz - 3.0f*xx - 3.0f*yy);
    bs[13] = -0.4570457994644658f  * x * (4.0f*zz - xx - yy);
    bs[14] =  1.445305721320277f   * zd * (xx - yy);
    bs[15] = -0.5900435899266435f  * x * (xx - 3.0f*yy);

    const float* sh = shs + i*48;
    float col[3];
    #pragma unroll
    for (int ch = 0; ch < 3; ++ch) {
        float acc = 0.5f;
        #pragma unroll
        for (int j = 0; j < 16; ++j) acc += bs[j] * sh[j*3 + ch];
        col[ch] = fmaxf(acc, 0.0f);
    }

    float alpha = 1.0f / (1.0f + expf(-alphas_raw[i]));
    float alpha_eff = valid ? alpha : 0.0f;

    g_depth[i] = depth;
    float* p = g_packed + i*12;
    p[0] = ux; p[1] = uy; p[2] = ci0; p[3] = ci1;
    p[4] = ci2; p[5] = alpha_eff; p[6] = col[0]; p[7] = col[1];
    p[8] = col[2]; p[9] = 0.0f; p[10] = 0.0f; p[11] = 0.0f;
}

// single-block bitonic argsort over depth, then gather packed data in sorted order
__global__ void sort_kernel()
{
    __shared__ float key[NG];
    __shared__ int   val[NG];
    int t = threadIdx.x;
    for (int i = t; i < NG; i += blockDim.x) { key[i] = g_depth[i]; val[i] = i; }
    __syncthreads();

    for (int k = 2; k <= NG; k <<= 1) {
        for (int j = k >> 1; j > 0; j >>= 1) {
            for (int i = t; i < NG; i += blockDim.x) {
                int ij = i ^ j;
                if (ij > i) {
                    bool up = ((i & k) == 0);
                    float ki = key[i], kj = key[ij];
                    bool doswap = up ? (ki > kj) : (ki < kj);
                    if (doswap) {
                        key[i] = kj; key[ij] = ki;
                        int vi = val[i]; val[i] = val[ij]; val[ij] = vi;
                    }
                }
            }
            __syncthreads();
        }
    }

    // gather into sorted stream
    float* dst = (float*)g_sorted;
    for (int e = t; e < NG * 12; e += blockDim.x) {
        int gi = e / 12, c = e - gi * 12;
        dst[e] = g_packed[val[gi] * 12 + c];
    }
}

__global__ void __launch_bounds__(64, 8) render_kernel(float* __restrict__ out)
{
    int tx = threadIdx.x & 7;
    int ty = threadIdx.x >> 3;
    int x = blockIdx.x * 8 + tx;
    int y = blockIdx.y * 8 + ty;
    float px = (float)x + 0.5f;
    float py = (float)y + 0.5f;

    float T = 1.0f;
    float cr = 0.0f, cg = 0.0f, cb = 0.0f;

    const float4* base = g_sorted;
    const float*  basef = (const float*)g_sorted;

    for (int i = 0; i < NG; ++i) {
        float4 A = __ldg(base + i*3);       // ux, uy, ci0, ci1
        float4 B = __ldg(base + i*3 + 1);   // ci2, alpha, col_r, col_g
        float  bcol = __ldg(basef + i*12 + 8);

        float dx = px - A.x;
        float dy = py - A.y;
        float power = -0.5f * (A.z*dx*dx + B.x*dy*dy) - A.w*dx*dy;
        if (power <= 0.0f) {
            float g = fminf(B.y * __expf(power), 0.99f);
            if (g >= (1.0f/255.0f)) {
                float w = T * g;
                cr = fmaf(w, B.z, cr);
                cg = fmaf(w, B.w, cg);
                cb = fmaf(w, bcol, cb);
                T *= (1.0f - g);
            }
        }
        if ((i & 31) == 31 && __all_sync(0xffffffffu, T < 1e-6f)) break;
    }

    out[0*(IMW*IMH) + y*IMW + x] = cr;
    out[1*(IMW*IMH) + y*IMW + x] = cg;
    out[2*(IMW*IMH) + y*IMW + x] = cb;
}

extern "C" void kernel_launch(void* const* d_in, const int* in_sizes, int n_in,
                              void* d_out, int out_size)
{
    const float* pws        = (const float*)d_in[0];
    const float* shs        = (const float*)d_in[1];
    const float* alphas_raw = (const float*)d_in[2];
    const float* scales_raw = (const float*)d_in[3];
    const float* rots_raw   = (const float*)d_in[4];
    // d_in[5] = us (unused by the reference)
    const float* Rcw        = (const float*)d_in[6];
    const float* tcw        = (const float*)d_in[7];

    float* out = (float*)d_out;
    float* areas_out = out + 3 * IMW * IMH;

    preprocess_kernel<<<(NG + 255) / 256, 256>>>(pws, shs, alphas_raw, scales_raw,
                                                 rots_raw, Rcw, tcw, areas_out);
    sort_kernel<<<1, 1024>>>();
    render_kernel<<<dim3(IMW/8, IMH/8), 64>>>(out);
}

// round 2
// speedup vs baseline: 8.1786x; 8.1786x over previous
#include <cuda_runtime.h>
#include <cuda_bf16.h>
#include <math.h>

#define NG 2048
#define IMW 128
#define IMH 128
#define FX 400.0f
#define FY 400.0f
#define CX 64.0f
#define CY 64.0f
#define NTILES 64          // 8x8 tiles of 16x16 px

// packed per-gaussian record (12 floats):
//  [0]ux [1]uy [2]cinv0 [3]cinv1 | [4]cinv2 [5]alpha [6]r [7]g | [8]b [9]wx [10]wy [11]pad
__device__ float  g_packed[NG * 12];
__device__ float  g_depth[NG];
__device__ float4 g_sorted[NG * 3];
__device__ int    tile_count[NTILES];
__device__ int    tile_list[NTILES * NG];

__constant__ float kSH_C0 = 0.28209479177387814f;
__constant__ float kSH_C1 = 0.4886025119029199f;

__global__ void preprocess_kernel(const float* __restrict__ pws,
                                  const float* __restrict__ shs,
                                  const float* __restrict__ alphas_raw,
                                  const float* __restrict__ scales_raw,
                                  const float* __restrict__ rots_raw,
                                  const float* __restrict__ Rcw,
                                  const float* __restrict__ tcw,
                                  float* __restrict__ areas_out)
{
    int i = blockIdx.x * blockDim.x + threadIdx.x;
    if (i >= NG) return;

    float R00 = Rcw[0], R01 = Rcw[1], R02 = Rcw[2];
    float R10 = Rcw[3], R11 = Rcw[4], R12 = Rcw[5];
    float R20 = Rcw[6], R21 = Rcw[7], R22 = Rcw[8];
    float t0 = tcw[0], t1 = tcw[1], t2 = tcw[2];

    float pwx = pws[i*3+0], pwy = pws[i*3+1], pwz = pws[i*3+2];

    float pc0 = R00*pwx + R01*pwy + R02*pwz + t0;
    float pc1 = R10*pwx + R11*pwy + R12*pwz + t1;
    float pc2 = R20*pwx + R21*pwy + R22*pwz + t2;

    float depth = pc2;
    bool valid = depth > 0.2f;
    float z = valid ? depth : 1.0f;

    float ux = FX * pc0 / z + CX;
    float uy = FY * pc1 / z + CY;

    float qw = rots_raw[i*4+0], qx = rots_raw[i*4+1], qy = rots_raw[i*4+2], qz = rots_raw[i*4+3];
    float qn = rsqrtf(qw*qw + qx*qx + qy*qy + qz*qz);
    qw *= qn; qx *= qn; qy *= qn; qz *= qn;

    float r00 = 1.0f - 2.0f*(qy*qy + qz*qz);
    float r01 = 2.0f*(qx*qy - qw*qz);
    float r02 = 2.0f*(qx*qz + qw*qy);
    float r10 = 2.0f*(qx*qy + qw*qz);
    float r11 = 1.0f - 2.0f*(qx*qx + qz*qz);
    float r12 = 2.0f*(qy*qz - qw*qx);
    float r20 = 2.0f*(qx*qz - qw*qy);
    float r21 = 2.0f*(qy*qz + qw*qx);
    float r22 = 1.0f - 2.0f*(qx*qx + qy*qy);

    float s0 = expf(scales_raw[i*3+0]);
    float s1 = expf(scales_raw[i*3+1]);
    float s2 = expf(scales_raw[i*3+2]);

    float m00 = r00*s0, m01 = r01*s1, m02 = r02*s2;
    float m10 = r10*s0, m11 = r11*s1, m12 = r12*s2;
    float m20 = r20*s0, m21 = r21*s1, m22 = r22*s2;

    float Sxx = m00*m00 + m01*m01 + m02*m02;
    float Sxy = m00*m10 + m01*m11 + m02*m12;
    float Sxz = m00*m20 + m01*m21 + m02*m22;
    float Syy = m10*m10 + m11*m11 + m12*m12;
    float Syz = m10*m20 + m11*m21 + m12*m22;
    float Szz = m20*m20 + m21*m21 + m22*m22;

    const float limx = 1.3f * 0.5f * (float)IMW / FX;
    const float limy = 1.3f * 0.5f * (float)IMH / FY;
    float tx = fminf(fmaxf(pc0 / z, -limx), limx) * z;
    float ty = fminf(fmaxf(pc1 / z, -limy), limy) * z;

    float j00 = FX / z;
    float j02 = -FX * tx / (z*z);
    float j11 = FY / z;
    float j12 = -FY * ty / (z*z);

    float T00 = j00*R00 + j02*R20;
    float T01 = j00*R01 + j02*R21;
    float T02 = j00*R02 + j02*R22;
    float T10 = j11*R10 + j12*R20;
    float T11 = j11*R11 + j12*R21;
    float T12 = j11*R12 + j12*R22;

    float u0 = T00*Sxx + T01*Sxy + T02*Sxz;
    float u1 = T00*Sxy + T01*Syy + T02*Syz;
    float u2 = T00*Sxz + T01*Syz + T02*Szz;
    float v0 = T10*Sxx + T11*Sxy + T12*Sxz;
    float v1 = T10*Sxy + T11*Syy + T12*Syz;
    float v2 = T10*Sxz + T11*Syz + T12*Szz;

    float a = u0*T00 + u1*T01 + u2*T02 + 0.3f;
    float b = u0*T10 + u1*T11 + u2*T12;
    float c = v0*T10 + v1*T11 + v2*T12 + 0.3f;

    float det = a*c - b*b;
    valid = valid && (det > 0.0f);
    float det_s = valid ? det : 1.0f;
    float ci0 = c / det_s;
    float ci1 = -b / det_s;
    float ci2 = a / det_s;

    float mid = 0.5f * (a + c);
    float disc = sqrtf(fmaxf(mid*mid - det, 0.1f));
    float ar0 = 3.0f * sqrtf(fmaxf(mid + disc, 0.0f));
    float ar1 = 3.0f * sqrtf(fmaxf(mid - disc, 0.0f));
    areas_out[2*i+0] = valid ? ar0 : 0.0f;
    areas_out[2*i+1] = valid ? ar1 : 0.0f;

    float twc0 = -(R00*t0 + R10*t1 + R20*t2);
    float twc1 = -(R01*t0 + R11*t1 + R21*t2);
    float twc2 = -(R02*t0 + R12*t1 + R22*t2);
    float dx = pwx - twc0, dy = pwy - twc1, dz = pwz - twc2;
    float dn = rsqrtf(dx*dx + dy*dy + dz*dz);
    float x = dx*dn, y = dy*dn, zd = dz*dn;

    float xx = x*x, yy = y*y, zz = zd*zd;
    float xy = x*y, yz = y*zd, xz = x*zd;

    float bs[16];
    bs[0]  = kSH_C0;
    bs[1]  = -kSH_C1 * y;
    bs[2]  =  kSH_C1 * zd;
    bs[3]  = -kSH_C1 * x;
    bs[4]  =  1.0925484305920792f  * xy;
    bs[5]  = -1.0925484305920792f  * yz;
    bs[6]  =  0.31539156525252005f * (2.0f*zz - xx - yy);
    bs[7]  = -1.0925484305920792f  * xz;
    bs[8]  =  0.5462742152960396f  * (xx - yy);
    bs[9]  = -0.5900435899266435f  * y * (3.0f*xx - yy);
    bs[10] =  2.890611442640554f   * xy * zd;
    bs[11] = -0.4570457994644658f  * y * (4.0f*zz - xx - yy);
    bs[12] =  0.3731763325901154f  * zd * (2.0f*zz - 3.0f*xx - 3.0f*yy);
    bs[13] = -0.4570457994644658f  * x * (4.0f*zz - xx - yy);
    bs[14] =  1.445305721320277f   * zd * (xx - yy);
    bs[15] = -0.5900435899266435f  * x * (xx - 3.0f*yy);

    // vectorized SH load: 48 floats = 12 float4
    float s[48];
    const float4* sh4 = (const float4*)(shs + i*48);
    #pragma unroll
    for (int j = 0; j < 12; ++j) {
        float4 v = __ldg(sh4 + j);
        s[4*j+0] = v.x; s[4*j+1] = v.y; s[4*j+2] = v.z; s[4*j+3] = v.w;
    }
    float col[3];
    #pragma unroll
    for (int ch = 0; ch < 3; ++ch) {
        float acc = 0.5f;
        #pragma unroll
        for (int j = 0; j < 16; ++j) acc += bs[j] * s[j*3 + ch];
        col[ch] = fmaxf(acc, 0.0f);
    }

    float alpha = 1.0f / (1.0f + expf(-alphas_raw[i]));
    float alpha_eff = valid ? alpha : 0.0f;

    // conservative bbox halfwidths for the exact inclusion ellipse
    //   q(dx,dy) <= tau  <=>  alpha*exp(power) >= 1/255
    // max|dx| = sqrt(tau * cinv2 / det(cinv)) = sqrt(tau * a)  (det(cinv)=1/det)
    float wx = -1.0f, wy = -1.0f;
    if (valid && alpha_eff >= (1.0f/255.0f)) {
        float tau = 2.0f * logf(255.0f * alpha_eff);
        if (tau > 0.0f) {
            wx = sqrtf(tau * a) + 0.05f;
            wy = sqrtf(tau * c) + 0.05f;
        }
    }

    g_depth[i] = depth;
    float* p = g_packed + i*12;
    p[0] = ux; p[1] = uy; p[2] = ci0; p[3] = ci1;
    p[4] = ci2; p[5] = alpha_eff; p[6] = col[0]; p[7] = col[1];
    p[8] = col[2]; p[9] = wx; p[10] = wy; p[11] = 0.0f;
}

// single-block bitonic argsort over depth, then gather packed data in sorted order
__global__ void sort_kernel()
{
    __shared__ float key[NG];
    __shared__ int   val[NG];
    int t = threadIdx.x;
    for (int i = t; i < NG; i += blockDim.x) { key[i] = g_depth[i]; val[i] = i; }
    __syncthreads();

    for (int k = 2; k <= NG; k <<= 1) {
        for (int j = k >> 1; j > 0; j >>= 1) {
            for (int i = t; i < NG; i += blockDim.x) {
                int ij = i ^ j;
                if (ij > i) {
                    bool up = ((i & k) == 0);
                    float ki = key[i], kj = key[ij];
                    bool doswap = up ? (ki > kj) : (ki < kj);
                    if (doswap) {
                        key[i] = kj; key[ij] = ki;
                        int vi = val[i]; val[i] = val[ij]; val[ij] = vi;
                    }
                }
            }
            __syncthreads();
        }
    }

    float* dst = (float*)g_sorted;
    for (int e = t; e < NG * 12; e += blockDim.x) {
        int gi = e / 12, c = e - gi * 12;
        dst[e] = g_packed[val[gi] * 12 + c];
    }
}

// one warp per tile: ordered compaction of sorted gaussians overlapping the tile
__global__ void bin_kernel()
{
    int warp = (blockIdx.x * blockDim.x + threadIdx.x) >> 5;
    int lane = threadIdx.x & 31;
    if (warp >= NTILES) return;

    float x0 = (float)((warp & 7) * 16) + 0.5f;
    float x1 = x0 + 15.0f;
    float y0 = (float)((warp >> 3) * 16) + 0.5f;
    float y1 = y0 + 15.0f;

    const float* pf = (const float*)g_sorted;
    int cnt = 0;
    for (int base = 0; base < NG; base += 32) {
        int i = base + lane;
        float ux = pf[i*12+0];
        float uy = pf[i*12+1];
        float wx = pf[i*12+9];
        float wy = pf[i*12+10];
        bool hit = (wx > 0.0f) &&
                   (ux - wx <= x1) && (ux + wx >= x0) &&
                   (uy - wy <= y1) && (uy + wy >= y0);
        unsigned m = __ballot_sync(0xffffffffu, hit);
        if (hit) {
            int rank = __popc(m & ((1u << lane) - 1u));
            tile_list[warp * NG + cnt + rank] = i;
        }
        cnt += __popc(m);
    }
    if (lane == 0) tile_count[warp] = cnt;
}

__global__ void __launch_bounds__(256) render_kernel(float* __restrict__ out)
{
    __shared__ float4 sA[256];
    __shared__ float4 sB[256];
    __shared__ float  sC[256];

    int tile = blockIdx.x;
    int tx0 = (tile & 7) * 16;
    int ty0 = (tile >> 3) * 16;
    int lx = threadIdx.x & 15;
    int ly = threadIdx.x >> 4;
    int x = tx0 + lx;
    int y = ty0 + ly;
    float px = (float)x + 0.5f;
    float py = (float)y + 0.5f;

    int count = tile_count[tile];
    const int* list = tile_list + tile * NG;

    float T = 1.0f;
    float cr = 0.0f, cg = 0.0f, cb = 0.0f;
    bool done = false;

    for (int base = 0; base < count; base += 256) {
        int nb = min(256, count - base);
        __syncthreads();
        if ((int)threadIdx.x < nb) {
            int gi = list[base + threadIdx.x];
            sA[threadIdx.x] = g_sorted[gi*3];
            sB[threadIdx.x] = g_sorted[gi*3 + 1];
            sC[threadIdx.x] = ((const float*)g_sorted)[gi*12 + 8];
        }
        __syncthreads();

        if (!done) {
            for (int j = 0; j < nb; ++j) {
                float4 A = sA[j];
                float4 B = sB[j];
                float dx = px - A.x;
                float dy = py - A.y;
                float power = -0.5f * (A.z*dx*dx + B.x*dy*dy) - A.w*dx*dy;
                if (power <= 0.0f) {
                    float g = fminf(B.y * __expf(power), 0.99f);
                    if (g >= (1.0f/255.0f)) {
                        float w = T * g;
                        cr = fmaf(w, B.z, cr);
                        cg = fmaf(w, B.w, cg);
                        cb = fmaf(w, sC[j], cb);
                        T *= (1.0f - g);
                    }
                }
            }
            if (T < 1e-6f) done = true;
        }
        if (__syncthreads_count(done) == 256) break;
    }

    out[0*(IMW*IMH) + y*IMW + x] = cr;
    out[1*(IMW*IMH) + y*IMW + x] = cg;
    out[2*(IMW*IMH) + y*IMW + x] = cb;
}

extern "C" void kernel_launch(void* const* d_in, const int* in_sizes, int n_in,
                              void* d_out, int out_size)
{
    const float* pws        = (const float*)d_in[0];
    const float* shs        = (const float*)d_in[1];
    const float* alphas_raw = (const float*)d_in[2];
    const float* scales_raw = (const float*)d_in[3];
    const float* rots_raw   = (const float*)d_in[4];
    // d_in[5] = us (unused by the reference)
    const float* Rcw        = (const float*)d_in[6];
    const float* tcw        = (const float*)d_in[7];

    float* out = (float*)d_out;
    float* areas_out = out + 3 * IMW * IMH;

    preprocess_kernel<<<(NG + 255) / 256, 256>>>(pws, shs, alphas_raw, scales_raw,
                                                 rots_raw, Rcw, tcw, areas_out);
    sort_kernel<<<1, 1024>>>();
    bin_kernel<<<8, 256>>>();
    render_kernel<<<NTILES, 256>>>(out);
}

// round 3
// speedup vs baseline: 17.3972x; 2.1272x over previous
#include <cuda_runtime.h>
#include <cuda_bf16.h>
#include <math.h>

#define NG 2048
#define IMW 128
#define IMH 128
#define FX 400.0f
#define FY 400.0f
#define CX 64.0f
#define CY 64.0f
#define NTILES 256         // 16x16 tiles of 8x8 px

// packed per-gaussian record (12 floats):
//  [0]ux [1]uy [2]cinv0 [3]cinv1 | [4]cinv2 [5]alpha [6]r [7]g | [8]b [9]wx [10]wy [11]pad
__device__ float  g_packed[NG * 12];
__device__ float  g_depth[NG];
__device__ float4 g_sorted[NG * 3];   // sorted stream (3 float4 per gaussian)
__device__ float4 g_bbox[NG];         // sorted: ux, uy, wx, wy

__constant__ float kSH_C0 = 0.28209479177387814f;
__constant__ float kSH_C1 = 0.4886025119029199f;

__global__ void preprocess_kernel(const float* __restrict__ pws,
                                  const float* __restrict__ shs,
                                  const float* __restrict__ alphas_raw,
                                  const float* __restrict__ scales_raw,
                                  const float* __restrict__ rots_raw,
                                  const float* __restrict__ Rcw,
                                  const float* __restrict__ tcw,
                                  float* __restrict__ areas_out)
{
    int i = blockIdx.x * blockDim.x + threadIdx.x;
    if (i >= NG) return;

    float R00 = Rcw[0], R01 = Rcw[1], R02 = Rcw[2];
    float R10 = Rcw[3], R11 = Rcw[4], R12 = Rcw[5];
    float R20 = Rcw[6], R21 = Rcw[7], R22 = Rcw[8];
    float t0 = tcw[0], t1 = tcw[1], t2 = tcw[2];

    float pwx = pws[i*3+0], pwy = pws[i*3+1], pwz = pws[i*3+2];

    float pc0 = R00*pwx + R01*pwy + R02*pwz + t0;
    float pc1 = R10*pwx + R11*pwy + R12*pwz + t1;
    float pc2 = R20*pwx + R21*pwy + R22*pwz + t2;

    float depth = pc2;
    bool valid = depth > 0.2f;
    float z = valid ? depth : 1.0f;
    float invz = __fdividef(1.0f, z);

    float ux = FX * pc0 * invz + CX;
    float uy = FY * pc1 * invz + CY;

    float qw = rots_raw[i*4+0], qx = rots_raw[i*4+1], qy = rots_raw[i*4+2], qz = rots_raw[i*4+3];
    float qn = rsqrtf(qw*qw + qx*qx + qy*qy + qz*qz);
    qw *= qn; qx *= qn; qy *= qn; qz *= qn;

    float r00 = 1.0f - 2.0f*(qy*qy + qz*qz);
    float r01 = 2.0f*(qx*qy - qw*qz);
    float r02 = 2.0f*(qx*qz + qw*qy);
    float r10 = 2.0f*(qx*qy + qw*qz);
    float r11 = 1.0f - 2.0f*(qx*qx + qz*qz);
    float r12 = 2.0f*(qy*qz - qw*qx);
    float r20 = 2.0f*(qx*qz - qw*qy);
    float r21 = 2.0f*(qy*qz + qw*qx);
    float r22 = 1.0f - 2.0f*(qx*qx + qy*qy);

    float s0 = __expf(scales_raw[i*3+0]);
    float s1 = __expf(scales_raw[i*3+1]);
    float s2 = __expf(scales_raw[i*3+2]);

    float m00 = r00*s0, m01 = r01*s1, m02 = r02*s2;
    float m10 = r10*s0, m11 = r11*s1, m12 = r12*s2;
    float m20 = r20*s0, m21 = r21*s1, m22 = r22*s2;

    float Sxx = m00*m00 + m01*m01 + m02*m02;
    float Sxy = m00*m10 + m01*m11 + m02*m12;
    float Sxz = m00*m20 + m01*m21 + m02*m22;
    float Syy = m10*m10 + m11*m11 + m12*m12;
    float Syz = m10*m20 + m11*m21 + m12*m22;
    float Szz = m20*m20 + m21*m21 + m22*m22;

    const float limx = 1.3f * 0.5f * (float)IMW / FX;
    const float limy = 1.3f * 0.5f * (float)IMH / FY;
    float tx = fminf(fmaxf(pc0 * invz, -limx), limx) * z;
    float ty = fminf(fmaxf(pc1 * invz, -limy), limy) * z;

    float j00 = FX * invz;
    float j02 = -FX * tx * invz * invz;
    float j11 = FY * invz;
    float j12 = -FY * ty * invz * invz;

    float T00 = j00*R00 + j02*R20;
    float T01 = j00*R01 + j02*R21;
    float T02 = j00*R02 + j02*R22;
    float T10 = j11*R10 + j12*R20;
    float T11 = j11*R11 + j12*R21;
    float T12 = j11*R12 + j12*R22;

    float u0 = T00*Sxx + T01*Sxy + T02*Sxz;
    float u1 = T00*Sxy + T01*Syy + T02*Syz;
    float u2 = T00*Sxz + T01*Syz + T02*Szz;
    float v0 = T10*Sxx + T11*Sxy + T12*Sxz;
    float v1 = T10*Sxy + T11*Syy + T12*Syz;
    float v2 = T10*Sxz + T11*Syz + T12*Szz;

    float a = u0*T00 + u1*T01 + u2*T02 + 0.3f;
    float b = u0*T10 + u1*T11 + u2*T12;
    float c = v0*T10 + v1*T11 + v2*T12 + 0.3f;

    float det = a*c - b*b;
    valid = valid && (det > 0.0f);
    float inv_det = __fdividef(1.0f, valid ? det : 1.0f);
    float ci0 = c * inv_det;
    float ci1 = -b * inv_det;
    float ci2 = a * inv_det;

    float mid = 0.5f * (a + c);
    float disc = sqrtf(fmaxf(mid*mid - det, 0.1f));
    float ar0 = 3.0f * sqrtf(fmaxf(mid + disc, 0.0f));
    float ar1 = 3.0f * sqrtf(fmaxf(mid - disc, 0.0f));
    areas_out[2*i+0] = valid ? ar0 : 0.0f;
    areas_out[2*i+1] = valid ? ar1 : 0.0f;

    float twc0 = -(R00*t0 + R10*t1 + R20*t2);
    float twc1 = -(R01*t0 + R11*t1 + R21*t2);
    float twc2 = -(R02*t0 + R12*t1 + R22*t2);
    float dx = pwx - twc0, dy = pwy - twc1, dz = pwz - twc2;
    float dn = rsqrtf(dx*dx + dy*dy + dz*dz);
    float x = dx*dn, y = dy*dn, zd = dz*dn;

    float xx = x*x, yy = y*y, zz = zd*zd;
    float xy = x*y, yz = y*zd, xz = x*zd;

    float bs[16];
    bs[0]  = kSH_C0;
    bs[1]  = -kSH_C1 * y;
    bs[2]  =  kSH_C1 * zd;
    bs[3]  = -kSH_C1 * x;
    bs[4]  =  1.0925484305920792f  * xy;
    bs[5]  = -1.0925484305920792f  * yz;
    bs[6]  =  0.31539156525252005f * (2.0f*zz - xx - yy);
    bs[7]  = -1.0925484305920792f  * xz;
    bs[8]  =  0.5462742152960396f  * (xx - yy);
    bs[9]  = -0.5900435899266435f  * y * (3.0f*xx - yy);
    bs[10] =  2.890611442640554f   * xy * zd;
    bs[11] = -0.4570457994644658f  * y * (4.0f*zz - xx - yy);
    bs[12] =  0.3731763325901154f  * zd * (2.0f*zz - 3.0f*xx - 3.0f*yy);
    bs[13] = -0.4570457994644658f  * x * (4.0f*zz - xx - yy);
    bs[14] =  1.445305721320277f   * zd * (xx - yy);
    bs[15] = -0.5900435899266435f  * x * (xx - 3.0f*yy);

    float s[48];
    const float4* sh4 = (const float4*)(shs + i*48);
    #pragma unroll
    for (int j = 0; j < 12; ++j) {
        float4 v = __ldg(sh4 + j);
        s[4*j+0] = v.x; s[4*j+1] = v.y; s[4*j+2] = v.z; s[4*j+3] = v.w;
    }
    float col[3];
    #pragma unroll
    for (int ch = 0; ch < 3; ++ch) {
        float acc = 0.5f;
        #pragma unroll
        for (int j = 0; j < 16; ++j) acc += bs[j] * s[j*3 + ch];
        col[ch] = fmaxf(acc, 0.0f);
    }

    float alpha = __fdividef(1.0f, 1.0f + __expf(-alphas_raw[i]));
    float alpha_eff = valid ? alpha : 0.0f;

    // conservative bbox halfwidths for the exact inclusion ellipse
    float wx = -1.0f, wy = -1.0f;
    if (valid && alpha_eff >= (1.0f/255.0f)) {
        float tau = 2.0f * __logf(255.0f * alpha_eff);
        if (tau > 0.0f) {
            wx = sqrtf(tau * a) + 0.05f;
            wy = sqrtf(tau * c) + 0.05f;
        }
    }

    g_depth[i] = depth;
    float* p = g_packed + i*12;
    p[0] = ux; p[1] = uy; p[2] = ci0; p[3] = ci1;
    p[4] = ci2; p[5] = alpha_eff; p[6] = col[0]; p[7] = col[1];
    p[8] = col[2]; p[9] = wx; p[10] = wy; p[11] = 0.0f;
}

// O(N^2) rank sort: 8 threads cooperate per gaussian. rank = #{j: d_j < d_i or (== and j<i)},
// matching stable argsort. Then scatter packed record to g_sorted[rank].
__global__ void __launch_bounds__(256) rank_scatter_kernel()
{
    __shared__ float sd[NG];
    int tid = threadIdx.x;
    #pragma unroll
    for (int j = tid; j < NG; j += 256) sd[j] = g_depth[j];
    __syncthreads();

    int gt = blockIdx.x * 256 + tid;   // 0 .. NG*8-1
    int i = gt >> 3;                   // gaussian index
    int p = gt & 7;                    // part 0..7 (= lane & 7)
    float d = sd[i];

    int r = 0;
    int start = p * (NG / 8);
    #pragma unroll 8
    for (int j = start; j < start + NG/8; ++j) {
        float dj = sd[j];
        r += (dj < d) || (dj == d && j < i);
    }
    r += __shfl_xor_sync(0xffffffffu, r, 1);
    r += __shfl_xor_sync(0xffffffffu, r, 2);
    r += __shfl_xor_sync(0xffffffffu, r, 4);

    const float* src = g_packed + i*12;
    float* dst = (float*)g_sorted + r*12;
    if (p < 4) {
        dst[3*p+0] = src[3*p+0];
        dst[3*p+1] = src[3*p+1];
        dst[3*p+2] = src[3*p+2];
    } else if (p == 4) {
        g_bbox[r] = make_float4(src[0], src[1], src[9], src[10]);
    }
}

// one block per 8x8 tile: warp 0 compacts sorted gaussians hitting this tile
// (ordered), then all 64 threads composite from smem-staged chunks.
__global__ void __launch_bounds__(64) render_kernel(float* __restrict__ out)
{
    __shared__ int   list[NG];
    __shared__ int   s_count;
    __shared__ float4 sA[64];
    __shared__ float4 sB[64];
    __shared__ float  sC[64];

    int tile = blockIdx.x;
    int tx0 = (tile & 15) * 8;
    int ty0 = (tile >> 4) * 8;
    int lx = threadIdx.x & 7;
    int ly = threadIdx.x >> 3;
    float px = (float)(tx0 + lx) + 0.5f;
    float py = (float)(ty0 + ly) + 0.5f;

    // tile pixel-center bounds
    float bx0 = (float)tx0 + 0.5f, bx1 = (float)tx0 + 7.5f;
    float by0 = (float)ty0 + 0.5f, by1 = (float)ty0 + 7.5f;

    int lane = threadIdx.x & 31;
    if (threadIdx.x < 32) {
        int cnt = 0;
        for (int base = 0; base < NG; base += 32) {
            float4 bb = g_bbox[base + lane];
            bool hit = (bb.z > 0.0f) &&
                       (bb.x - bb.z <= bx1) && (bb.x + bb.z >= bx0) &&
                       (bb.y - bb.w <= by1) && (bb.y + bb.w >= by0);
            unsigned m = __ballot_sync(0xffffffffu, hit);
            if (hit) {
                int rank = __popc(m & ((1u << lane) - 1u));
                list[cnt + rank] = base + lane;
            }
            cnt += __popc(m);
        }
        if (lane == 0) s_count = cnt;
    }
    __syncthreads();

    int count = s_count;
    float T = 1.0f;
    float cr = 0.0f, cg = 0.0f, cb = 0.0f;
    bool done = false;

    for (int base = 0; base < count; base += 64) {
        int nb = min(64, count - base);
        __syncthreads();
        if ((int)threadIdx.x < nb) {
            int gi = list[base + threadIdx.x];
            sA[threadIdx.x] = g_sorted[gi*3];
            sB[threadIdx.x] = g_sorted[gi*3 + 1];
            sC[threadIdx.x] = ((const float*)g_sorted)[gi*12 + 8];
        }
        __syncthreads();

        if (!done) {
            for (int j = 0; j < nb; ++j) {
                float4 A = sA[j];
                float4 B = sB[j];
                float dx = px - A.x;
                float dy = py - A.y;
                float power = -0.5f * (A.z*dx*dx + B.x*dy*dy) - A.w*dx*dy;
                if (power <= 0.0f) {
                    float g = fminf(B.y * __expf(power), 0.99f);
                    if (g >= (1.0f/255.0f)) {
                        float w = T * g;
                        cr = fmaf(w, B.z, cr);
                        cg = fmaf(w, B.w, cg);
                        cb = fmaf(w, sC[j], cb);
                        T *= (1.0f - g);
                    }
                }
            }
            if (T < 1e-6f) done = true;
        }
        if (__syncthreads_count(done) == 64) break;
    }

    int x = tx0 + lx, y = ty0 + ly;
    out[0*(IMW*IMH) + y*IMW + x] = cr;
    out[1*(IMW*IMH) + y*IMW + x] = cg;
    out[2*(IMW*IMH) + y*IMW + x] = cb;
}

extern "C" void kernel_launch(void* const* d_in, const int* in_sizes, int n_in,
                              void* d_out, int out_size)
{
    const float* pws        = (const float*)d_in[0];
    const float* shs        = (const float*)d_in[1];
    const float* alphas_raw = (const float*)d_in[2];
    const float* scales_raw = (const float*)d_in[3];
    const float* rots_raw   = (const float*)d_in[4];
    // d_in[5] = us (unused by the reference)
    const float* Rcw        = (const float*)d_in[6];
    const float* tcw        = (const float*)d_in[7];

    float* out = (float*)d_out;
    float* areas_out = out + 3 * IMW * IMH;

    preprocess_kernel<<<16, 128>>>(pws, shs, alphas_raw, scales_raw,
                                   rots_raw, Rcw, tcw, areas_out);
    rank_scatter_kernel<<<NG * 8 / 256, 256>>>();
    render_kernel<<<NTILES, 64>>>(out);
}

// round 4
// speedup vs baseline: 22.9000x; 1.3163x over previous
#include <cuda_runtime.h>
#include <cuda_bf16.h>
#include <math.h>

#define NG 2048
#define IMW 128
#define IMH 128
#define FX 400.0f
#define FY 400.0f
#define CX 64.0f
#define CY 64.0f
#define NBLOCKS 256        // one 8x8 tile per block
#define NTHREADS 64

// packed per-gaussian record (3 float4):
//  [0]ux [1]uy [2]cinv0 [3]cinv1 | [4]cinv2 [5]alpha [6]r [7]g | [8]b [9]wx [10]wy [11]pad
__device__ float4 g_packed4[NG * 3];
__device__ float  g_depth[NG];
__device__ float4 g_sorted[NG * 3];   // sorted stream
__device__ float4 g_bbox[NG];         // sorted: ux, uy, wx, wy

__device__ unsigned bar_cnt = 0;
__device__ volatile unsigned bar_gen = 0;

__device__ __forceinline__ void grid_barrier()
{
    __syncthreads();
    if (threadIdx.x == 0) {
        unsigned gen = bar_gen;
        __threadfence();
        unsigned arrived = atomicAdd(&bar_cnt, 1u);
        if (arrived == gridDim.x - 1) {
            bar_cnt = 0;
            __threadfence();
            bar_gen = gen + 1;
        } else {
            while (bar_gen == gen) __nanosleep(32);
            __threadfence();
        }
    }
    __syncthreads();
}

__constant__ float kSH_C0 = 0.28209479177387814f;
__constant__ float kSH_C1 = 0.4886025119029199f;

__global__ void __launch_bounds__(NTHREADS) fused_kernel(
    const float* __restrict__ pws,
    const float* __restrict__ shs,
    const float* __restrict__ alphas_raw,
    const float* __restrict__ scales_raw,
    const float* __restrict__ rots_raw,
    const float* __restrict__ Rcw,
    const float* __restrict__ tcw,
    float* __restrict__ out)
{
    __shared__ float  sd[NG];       // depths (phase 2)
    __shared__ int    list[NG];     // tile list (phase 3)
    __shared__ int    s_count;
    __shared__ float4 sA[NTHREADS];
    __shared__ float4 sB[NTHREADS];
    __shared__ float  sC[NTHREADS];

    const int tid = threadIdx.x;
    const int gid = blockIdx.x * NTHREADS + tid;
    float* areas_out = out + 3 * IMW * IMH;

    // ---------------- Phase 1: preprocess (4 threads / gaussian) -------------
    if (gid < NG * 4) {
        int i = gid >> 2;
        int q = gid & 3;

        float R00 = Rcw[0], R01 = Rcw[1], R02 = Rcw[2];
        float R10 = Rcw[3], R11 = Rcw[4], R12 = Rcw[5];
        float R20 = Rcw[6], R21 = Rcw[7], R22 = Rcw[8];
        float t0 = tcw[0], t1 = tcw[1], t2 = tcw[2];

        float pwx = pws[i*3+0], pwy = pws[i*3+1], pwz = pws[i*3+2];

        if (q < 3) {
            // color lane: channel q
            float twc0 = -(R00*t0 + R10*t1 + R20*t2);
            float twc1 = -(R01*t0 + R11*t1 + R21*t2);
            float twc2 = -(R02*t0 + R12*t1 + R22*t2);
            float dx = pwx - twc0, dy = pwy - twc1, dz = pwz - twc2;
            float dn = rsqrtf(dx*dx + dy*dy + dz*dz);
            float x = dx*dn, y = dy*dn, zd = dz*dn;

            float xx = x*x, yy = y*y, zz = zd*zd;
            float xy = x*y, yz = y*zd, xz = x*zd;

            float bs[16];
            bs[0]  = kSH_C0;
            bs[1]  = -kSH_C1 * y;
            bs[2]  =  kSH_C1 * zd;
            bs[3]  = -kSH_C1 * x;
            bs[4]  =  1.0925484305920792f  * xy;
            bs[5]  = -1.0925484305920792f  * yz;
            bs[6]  =  0.31539156525252005f * (2.0f*zz - xx - yy);
            bs[7]  = -1.0925484305920792f  * xz;
            bs[8]  =  0.5462742152960396f  * (xx - yy);
            bs[9]  = -0.5900435899266435f  * y * (3.0f*xx - yy);
            bs[10] =  2.890611442640554f   * xy * zd;
            bs[11] = -0.4570457994644658f  * y * (4.0f*zz - xx - yy);
            bs[12] =  0.3731763325901154f  * zd * (2.0f*zz - 3.0f*xx - 3.0f*yy);
            bs[13] = -0.4570457994644658f  * x * (4.0f*zz - xx - yy);
            bs[14] =  1.445305721320277f   * zd * (xx - yy);
            bs[15] = -0.5900435899266435f  * x * (xx - 3.0f*yy);

            const float* sh = shs + i*48 + q;
            float v[16];
            #pragma unroll
            for (int j = 0; j < 16; ++j) v[j] = __ldg(sh + j*3);
            float acc = 0.5f;
            #pragma unroll
            for (int j = 0; j < 16; ++j) acc = fmaf(bs[j], v[j], acc);
            ((float*)g_packed4)[i*12 + 6 + q] = fmaxf(acc, 0.0f);
        } else {
            // geometry lane
            float pc0 = R00*pwx + R01*pwy + R02*pwz + t0;
            float pc1 = R10*pwx + R11*pwy + R12*pwz + t1;
            float pc2 = R20*pwx + R21*pwy + R22*pwz + t2;

            float depth = pc2;
            bool valid = depth > 0.2f;
            float z = valid ? depth : 1.0f;
            float invz = __fdividef(1.0f, z);

            float ux = FX * pc0 * invz + CX;
            float uy = FY * pc1 * invz + CY;

            float qw = rots_raw[i*4+0], qx = rots_raw[i*4+1];
            float qy = rots_raw[i*4+2], qz = rots_raw[i*4+3];
            float qn = rsqrtf(qw*qw + qx*qx + qy*qy + qz*qz);
            qw *= qn; qx *= qn; qy *= qn; qz *= qn;

            float r00 = 1.0f - 2.0f*(qy*qy + qz*qz);
            float r01 = 2.0f*(qx*qy - qw*qz);
            float r02 = 2.0f*(qx*qz + qw*qy);
            float r10 = 2.0f*(qx*qy + qw*qz);
            float r11 = 1.0f - 2.0f*(qx*qx + qz*qz);
            float r12 = 2.0f*(qy*qz - qw*qx);
            float r20 = 2.0f*(qx*qz - qw*qy);
            float r21 = 2.0f*(qy*qz + qw*qx);
            float r22 = 1.0f - 2.0f*(qx*qx + qy*qy);

            float s0 = __expf(scales_raw[i*3+0]);
            float s1 = __expf(scales_raw[i*3+1]);
            float s2 = __expf(scales_raw[i*3+2]);

            float m00 = r00*s0, m01 = r01*s1, m02 = r02*s2;
            float m10 = r10*s0, m11 = r11*s1, m12 = r12*s2;
            float m20 = r20*s0, m21 = r21*s1, m22 = r22*s2;

            float Sxx = m00*m00 + m01*m01 + m02*m02;
            float Sxy = m00*m10 + m01*m11 + m02*m12;
            float Sxz = m00*m20 + m01*m21 + m02*m22;
            float Syy = m10*m10 + m11*m11 + m12*m12;
            float Syz = m10*m20 + m11*m21 + m12*m22;
            float Szz = m20*m20 + m21*m21 + m22*m22;

            const float limx = 1.3f * 0.5f * (float)IMW / FX;
            const float limy = 1.3f * 0.5f * (float)IMH / FY;
            float txl = fminf(fmaxf(pc0 * invz, -limx), limx) * z;
            float tyl = fminf(fmaxf(pc1 * invz, -limy), limy) * z;

            float j00 = FX * invz;
            float j02 = -FX * txl * invz * invz;
            float j11 = FY * invz;
            float j12 = -FY * tyl * invz * invz;

            float T00 = j00*R00 + j02*R20;
            float T01 = j00*R01 + j02*R21;
            float T02 = j00*R02 + j02*R22;
            float T10 = j11*R10 + j12*R20;
            float T11 = j11*R11 + j12*R21;
            float T12 = j11*R12 + j12*R22;

            float u0 = T00*Sxx + T01*Sxy + T02*Sxz;
            float u1 = T00*Sxy + T01*Syy + T02*Syz;
            float u2 = T00*Sxz + T01*Syz + T02*Szz;
            float v0 = T10*Sxx + T11*Sxy + T12*Sxz;
            float v1 = T10*Sxy + T11*Syy + T12*Syz;
            float v2 = T10*Sxz + T11*Syz + T12*Szz;

            float a = u0*T00 + u1*T01 + u2*T02 + 0.3f;
            float b = u0*T10 + u1*T11 + u2*T12;
            float c = v0*T10 + v1*T11 + v2*T12 + 0.3f;

            float det = a*c - b*b;
            valid = valid && (det > 0.0f);
            float inv_det = __fdividef(1.0f, valid ? det : 1.0f);
            float ci0 = c * inv_det;
            float ci1 = -b * inv_det;
            float ci2 = a * inv_det;

            float mid = 0.5f * (a + c);
            float disc = sqrtf(fmaxf(mid*mid - det, 0.1f));
            float ar0 = 3.0f * sqrtf(fmaxf(mid + disc, 0.0f));
            float ar1 = 3.0f * sqrtf(fmaxf(mid - disc, 0.0f));
            areas_out[2*i+0] = valid ? ar0 : 0.0f;
            areas_out[2*i+1] = valid ? ar1 : 0.0f;

            float alpha = __fdividef(1.0f, 1.0f + __expf(-alphas_raw[i]));
            float alpha_eff = valid ? alpha : 0.0f;

            float wx = -1.0f, wy = -1.0f;
            if (valid && alpha_eff >= (1.0f/255.0f)) {
                float tau = 2.0f * __logf(255.0f * alpha_eff);
                if (tau > 0.0f) {
                    wx = sqrtf(tau * a) + 0.05f;
                    wy = sqrtf(tau * c) + 0.05f;
                }
            }

            g_depth[i] = depth;
            float* p = (float*)(g_packed4 + i*3);
            p[0] = ux; p[1] = uy; p[2] = ci0; p[3] = ci1;
            p[4] = ci2; p[5] = alpha_eff;
            p[9] = wx; p[10] = wy; p[11] = 0.0f;
        }
    }

    grid_barrier();

    // ---------------- Phase 2: rank sort + scatter (8 threads / gaussian) ----
    {
        #pragma unroll
        for (int j = tid; j < NG; j += NTHREADS) sd[j] = g_depth[j];
        __syncthreads();

        int gt = blockIdx.x * NTHREADS + tid;  // 0 .. NG*8-1
        int i = gt >> 3;
        int p = gt & 7;
        float d = sd[i];

        int r = 0;
        #pragma unroll 8
        for (int j = p; j < NG; j += 8) {     // interleaved: bank-conflict-free
            float dj = sd[j];
            r += (dj < d) || (dj == d && j < i);
        }
        r += __shfl_xor_sync(0xffffffffu, r, 1);
        r += __shfl_xor_sync(0xffffffffu, r, 2);
        r += __shfl_xor_sync(0xffffffffu, r, 4);

        if (p < 3) {
            g_sorted[r*3 + p] = g_packed4[i*3 + p];
        } else if (p == 3) {
            float4 A = g_packed4[i*3 + 0];
            float4 C = g_packed4[i*3 + 2];
            g_bbox[r] = make_float4(A.x, A.y, C.y, C.z);
        }
    }

    grid_barrier();

    // ---------------- Phase 3: bin + composite (one 8x8 tile / block) --------
    const int tile = blockIdx.x;
    const int tx0 = (tile & 15) * 8;
    const int ty0 = (tile >> 4) * 8;
    const int lx = tid & 7;
    const int ly = tid >> 3;
    const float px = (float)(tx0 + lx) + 0.5f;
    const float py = (float)(ty0 + ly) + 0.5f;

    const float bx0 = (float)tx0 + 0.5f, bx1 = (float)tx0 + 7.5f;
    const float by0 = (float)ty0 + 0.5f, by1 = (float)ty0 + 7.5f;

    const int lane = tid & 31;
    if (tid < 32) {
        int cnt = 0;
        for (int base = 0; base < NG; base += 256) {
            float4 bb[8];
            #pragma unroll
            for (int u = 0; u < 8; ++u) bb[u] = g_bbox[base + u*32 + lane];
            #pragma unroll
            for (int u = 0; u < 8; ++u) {
                bool hit = (bb[u].z > 0.0f) &&
                           (bb[u].x - bb[u].z <= bx1) && (bb[u].x + bb[u].z >= bx0) &&
                           (bb[u].y - bb[u].w <= by1) && (bb[u].y + bb[u].w >= by0);
                unsigned m = __ballot_sync(0xffffffffu, hit);
                if (hit) {
                    int rank = __popc(m & ((1u << lane) - 1u));
                    list[cnt + rank] = base + u*32 + lane;
                }
                cnt += __popc(m);
            }
        }
        if (lane == 0) s_count = cnt;
    }
    __syncthreads();

    int count = s_count;
    float T = 1.0f;
    float cr = 0.0f, cg = 0.0f, cb = 0.0f;
    bool done = false;

    for (int base = 0; base < count; base += NTHREADS) {
        int nb = min(NTHREADS, count - base);
        __syncthreads();
        if (tid < nb) {
            int gi = list[base + tid];
            sA[tid] = g_sorted[gi*3];
            sB[tid] = g_sorted[gi*3 + 1];
            sC[tid] = ((const float*)g_sorted)[gi*12 + 8];
        }
        __syncthreads();

        if (!done) {
            for (int j = 0; j < nb; ++j) {
                float4 A = sA[j];
                float4 B = sB[j];
                float dx = px - A.x;
                float dy = py - A.y;
                float power = -0.5f * (A.z*dx*dx + B.x*dy*dy) - A.w*dx*dy;
                if (power <= 0.0f) {
                    float g = fminf(B.y * __expf(power), 0.99f);
                    if (g >= (1.0f/255.0f)) {
                        float w = T * g;
                        cr = fmaf(w, B.z, cr);
                        cg = fmaf(w, B.w, cg);
                        cb = fmaf(w, sC[j], cb);
                        T *= (1.0f - g);
                    }
                }
            }
            if (T < 1e-6f) done = true;
        }
        if (__syncthreads_count(done) == NTHREADS) break;
    }

    int x = tx0 + lx, y = ty0 + ly;
    out[0*(IMW*IMH) + y*IMW + x] = cr;
    out[1*(IMW*IMH) + y*IMW + x] = cg;
    out[2*(IMW*IMH) + y*IMW + x] = cb;
}

extern "C" void kernel_launch(void* const* d_in, const int* in_sizes, int n_in,
                              void* d_out, int out_size)
{
    const float* pws        = (const float*)d_in[0];
    const float* shs        = (const float*)d_in[1];
    const float* alphas_raw = (const float*)d_in[2];
    const float* scales_raw = (const float*)d_in[3];
    const float* rots_raw   = (const float*)d_in[4];
    // d_in[5] = us (unused by the reference)
    const float* Rcw        = (const float*)d_in[6];
    const float* tcw        = (const float*)d_in[7];

    float* out = (float*)d_out;

    fused_kernel<<<NBLOCKS, NTHREADS>>>(pws, shs, alphas_raw, scales_raw,
                                        rots_raw, Rcw, tcw, out);
}

// round 5
// speedup vs baseline: 35.1133x; 1.5333x over previous
#include <cuda_runtime.h>
#include <cuda_bf16.h>
#include <math.h>

#define NG 2048
#define IMW 128
#define IMH 128
#define FX 400.0f
#define FY 400.0f
#define CX 64.0f
#define CY 64.0f
#define NBLOCKS 256        // one 8x8 tile per block
#define NTHREADS 256       // 4 depth-segments x 64 pixels

// packed per-gaussian record (3 float4):
//  [0]ux [1]uy [2]cinv0 [3]cinv1 | [4]cinv2 [5]alpha [6]r [7]g | [8]b [9]wx [10]wy [11]pad
__device__ float4 g_packed4[NG * 3];
__device__ float  g_depth[NG];
__device__ float4 g_sorted[NG * 3];   // sorted stream
__device__ float4 g_bbox[NG];         // sorted: ux, uy, wx, wy

__device__ unsigned bar_cnt = 0;
__device__ volatile unsigned bar_gen = 0;

__device__ __forceinline__ void grid_barrier()
{
    __syncthreads();
    if (threadIdx.x == 0) {
        unsigned gen = bar_gen;
        __threadfence();
        unsigned arrived = atomicAdd(&bar_cnt, 1u);
        if (arrived == gridDim.x - 1) {
            bar_cnt = 0;
            __threadfence();
            bar_gen = gen + 1;
        } else {
            while (bar_gen == gen) __nanosleep(32);
            __threadfence();
        }
    }
    __syncthreads();
}

__constant__ float kSH_C0 = 0.28209479177387814f;
__constant__ float kSH_C1 = 0.4886025119029199f;

__global__ void __launch_bounds__(NTHREADS) fused_kernel(
    const float* __restrict__ pws,
    const float* __restrict__ shs,
    const float* __restrict__ alphas_raw,
    const float* __restrict__ scales_raw,
    const float* __restrict__ rots_raw,
    const float* __restrict__ Rcw,
    const float* __restrict__ tcw,
    float* __restrict__ out)
{
    __shared__ float  sd[NG];         // depths (phase 2)
    __shared__ int    list[NG];       // tile list (phase 3/4)
    __shared__ int    wcnt[9];
    __shared__ float4 stageA[4][64];
    __shared__ float4 stageB[4][64];
    __shared__ float  stageC[4][64];
    __shared__ float4 part[4][64];    // (r,g,b,T) per segment per pixel

    const int tid = threadIdx.x;
    float* areas_out = out + 3 * IMW * IMH;

    // ---------------- Phase 1: preprocess (warp 0 of each block; 4 thr/gauss)
    if (tid < 32) {
        int unit = blockIdx.x * 32 + tid;    // 8192 units
        int i = unit >> 2;
        int q = unit & 3;

        float R00 = Rcw[0], R01 = Rcw[1], R02 = Rcw[2];
        float R10 = Rcw[3], R11 = Rcw[4], R12 = Rcw[5];
        float R20 = Rcw[6], R21 = Rcw[7], R22 = Rcw[8];
        float t0 = tcw[0], t1 = tcw[1], t2 = tcw[2];

        float pwx = pws[i*3+0], pwy = pws[i*3+1], pwz = pws[i*3+2];

        if (q < 3) {
            // color lane: channel q
            float twc0 = -(R00*t0 + R10*t1 + R20*t2);
            float twc1 = -(R01*t0 + R11*t1 + R21*t2);
            float twc2 = -(R02*t0 + R12*t1 + R22*t2);
            float dx = pwx - twc0, dy = pwy - twc1, dz = pwz - twc2;
            float dn = rsqrtf(dx*dx + dy*dy + dz*dz);
            float x = dx*dn, y = dy*dn, zd = dz*dn;

            float xx = x*x, yy = y*y, zz = zd*zd;
            float xy = x*y, yz = y*zd, xz = x*zd;

            float bs[16];
            bs[0]  = kSH_C0;
            bs[1]  = -kSH_C1 * y;
            bs[2]  =  kSH_C1 * zd;
            bs[3]  = -kSH_C1 * x;
            bs[4]  =  1.0925484305920792f  * xy;
            bs[5]  = -1.0925484305920792f  * yz;
            bs[6]  =  0.31539156525252005f * (2.0f*zz - xx - yy);
            bs[7]  = -1.0925484305920792f  * xz;
            bs[8]  =  0.5462742152960396f  * (xx - yy);
            bs[9]  = -0.5900435899266435f  * y * (3.0f*xx - yy);
            bs[10] =  2.890611442640554f   * xy * zd;
            bs[11] = -0.4570457994644658f  * y * (4.0f*zz - xx - yy);
            bs[12] =  0.3731763325901154f  * zd * (2.0f*zz - 3.0f*xx - 3.0f*yy);
            bs[13] = -0.4570457994644658f  * x * (4.0f*zz - xx - yy);
            bs[14] =  1.445305721320277f   * zd * (xx - yy);
            bs[15] = -0.5900435899266435f  * x * (xx - 3.0f*yy);

            const float* sh = shs + i*48 + q;
            float v[16];
            #pragma unroll
            for (int j = 0; j < 16; ++j) v[j] = __ldg(sh + j*3);
            float acc = 0.5f;
            #pragma unroll
            for (int j = 0; j < 16; ++j) acc = fmaf(bs[j], v[j], acc);
            ((float*)g_packed4)[i*12 + 6 + q] = fmaxf(acc, 0.0f);
        } else {
            // geometry lane
            float pc0 = R00*pwx + R01*pwy + R02*pwz + t0;
            float pc1 = R10*pwx + R11*pwy + R12*pwz + t1;
            float pc2 = R20*pwx + R21*pwy + R22*pwz + t2;

            float depth = pc2;
            bool valid = depth > 0.2f;
            float z = valid ? depth : 1.0f;
            float invz = __fdividef(1.0f, z);

            float ux = FX * pc0 * invz + CX;
            float uy = FY * pc1 * invz + CY;

            float qw = rots_raw[i*4+0], qx = rots_raw[i*4+1];
            float qy = rots_raw[i*4+2], qz = rots_raw[i*4+3];
            float qn = rsqrtf(qw*qw + qx*qx + qy*qy + qz*qz);
            qw *= qn; qx *= qn; qy *= qn; qz *= qn;

            float r00 = 1.0f - 2.0f*(qy*qy + qz*qz);
            float r01 = 2.0f*(qx*qy - qw*qz);
            float r02 = 2.0f*(qx*qz + qw*qy);
            float r10 = 2.0f*(qx*qy + qw*qz);
            float r11 = 1.0f - 2.0f*(qx*qx + qz*qz);
            float r12 = 2.0f*(qy*qz - qw*qx);
            float r20 = 2.0f*(qx*qz - qw*qy);
            float r21 = 2.0f*(qy*qz + qw*qx);
            float r22 = 1.0f - 2.0f*(qx*qx + qy*qy);

            float s0 = __expf(scales_raw[i*3+0]);
            float s1 = __expf(scales_raw[i*3+1]);
            float s2 = __expf(scales_raw[i*3+2]);

            float m00 = r00*s0, m01 = r01*s1, m02 = r02*s2;
            float m10 = r10*s0, m11 = r11*s1, m12 = r12*s2;
            float m20 = r20*s0, m21 = r21*s1, m22 = r22*s2;

            float Sxx = m00*m00 + m01*m01 + m02*m02;
            float Sxy = m00*m10 + m01*m11 + m02*m12;
            float Sxz = m00*m20 + m01*m21 + m02*m22;
            float Syy = m10*m10 + m11*m11 + m12*m12;
            float Syz = m10*m20 + m11*m21 + m12*m22;
            float Szz = m20*m20 + m21*m21 + m22*m22;

            const float limx = 1.3f * 0.5f * (float)IMW / FX;
            const float limy = 1.3f * 0.5f * (float)IMH / FY;
            float txl = fminf(fmaxf(pc0 * invz, -limx), limx) * z;
            float tyl = fminf(fmaxf(pc1 * invz, -limy), limy) * z;

            float j00 = FX * invz;
            float j02 = -FX * txl * invz * invz;
            float j11 = FY * invz;
            float j12 = -FY * tyl * invz * invz;

            float T00 = j00*R00 + j02*R20;
            float T01 = j00*R01 + j02*R21;
            float T02 = j00*R02 + j02*R22;
            float T10 = j11*R10 + j12*R20;
            float T11 = j11*R11 + j12*R21;
            float T12 = j11*R12 + j12*R22;

            float u0 = T00*Sxx + T01*Sxy + T02*Sxz;
            float u1 = T00*Sxy + T01*Syy + T02*Syz;
            float u2 = T00*Sxz + T01*Syz + T02*Szz;
            float v0 = T10*Sxx + T11*Sxy + T12*Sxz;
            float v1 = T10*Sxy + T11*Syy + T12*Syz;
            float v2 = T10*Sxz + T11*Syz + T12*Szz;

            float a = u0*T00 + u1*T01 + u2*T02 + 0.3f;
            float b = u0*T10 + u1*T11 + u2*T12;
            float c = v0*T10 + v1*T11 + v2*T12 + 0.3f;

            float det = a*c - b*b;
            valid = valid && (det > 0.0f);
            float inv_det = __fdividef(1.0f, valid ? det : 1.0f);
            float ci0 = c * inv_det;
            float ci1 = -b * inv_det;
            float ci2 = a * inv_det;

            float mid = 0.5f * (a + c);
            float disc = sqrtf(fmaxf(mid*mid - det, 0.1f));
            float ar0 = 3.0f * sqrtf(fmaxf(mid + disc, 0.0f));
            float ar1 = 3.0f * sqrtf(fmaxf(mid - disc, 0.0f));
            areas_out[2*i+0] = valid ? ar0 : 0.0f;
            areas_out[2*i+1] = valid ? ar1 : 0.0f;

            float alpha = __fdividef(1.0f, 1.0f + __expf(-alphas_raw[i]));
            float alpha_eff = valid ? alpha : 0.0f;

            float wx = -1.0f, wy = -1.0f;
            if (valid && alpha_eff >= (1.0f/255.0f)) {
                float tau = 2.0f * __logf(255.0f * alpha_eff);
                if (tau > 0.0f) {
                    wx = sqrtf(tau * a) + 0.05f;
                    wy = sqrtf(tau * c) + 0.05f;
                }
            }

            g_depth[i] = depth;
            float* p = (float*)(g_packed4 + i*3);
            p[0] = ux; p[1] = uy; p[2] = ci0; p[3] = ci1;
            p[4] = ci2; p[5] = alpha_eff;
            p[9] = wx; p[10] = wy; p[11] = 0.0f;
        }
    }

    grid_barrier();

    // ---------------- Phase 2: rank sort + scatter (32 threads / gaussian) ---
    {
        #pragma unroll
        for (int j = tid; j < NG; j += NTHREADS) sd[j] = g_depth[j];
        __syncthreads();

        int lane = tid & 31;
        int i = blockIdx.x * 8 + (tid >> 5);   // one gaussian per warp
        float d = sd[i];

        int r = 0;
        #pragma unroll 8
        for (int j = lane; j < NG; j += 32) {  // stride-32: conflict-free
            float dj = sd[j];
            r += (dj < d) || (dj == d && j < i);
        }
        #pragma unroll
        for (int o = 16; o > 0; o >>= 1) r += __shfl_xor_sync(0xffffffffu, r, o);

        if (lane < 3) {
            g_sorted[r*3 + lane] = g_packed4[i*3 + lane];
        } else if (lane == 3) {
            float4 A = g_packed4[i*3 + 0];
            float4 C = g_packed4[i*3 + 2];
            g_bbox[r] = make_float4(A.x, A.y, C.y, C.z);
        }
    }

    grid_barrier();

    // ---------------- Phase 3: binning (8 warps, order-preserving compaction)
    const int tile = blockIdx.x;
    const int tx0 = (tile & 15) * 8;
    const int ty0 = (tile >> 4) * 8;
    const float bx0 = (float)tx0 + 0.5f, bx1 = (float)tx0 + 7.5f;
    const float by0 = (float)ty0 + 0.5f, by1 = (float)ty0 + 7.5f;

    {
        int w = tid >> 5, lane = tid & 31;
        int base0 = w * (NG / 8);
        float4 bb[8];
        unsigned mk[8];
        #pragma unroll
        for (int u = 0; u < 8; ++u) bb[u] = g_bbox[base0 + u*32 + lane];
        int cnt = 0;
        #pragma unroll
        for (int u = 0; u < 8; ++u) {
            bool hit = (bb[u].z > 0.0f) &&
                       (bb[u].x - bb[u].z <= bx1) && (bb[u].x + bb[u].z >= bx0) &&
                       (bb[u].y - bb[u].w <= by1) && (bb[u].y + bb[u].w >= by0);
            mk[u] = __ballot_sync(0xffffffffu, hit);
            cnt += __popc(mk[u]);
        }
        if (lane == 0) wcnt[w] = cnt;
        __syncthreads();
        if (tid == 0) {
            int acc = 0;
            #pragma unroll
            for (int w2 = 0; w2 < 8; ++w2) { int t = wcnt[w2]; wcnt[w2] = acc; acc += t; }
            wcnt[8] = acc;
        }
        __syncthreads();
        int off = wcnt[w];
        #pragma unroll
        for (int u = 0; u < 8; ++u) {
            if ((mk[u] >> lane) & 1u) {
                int rank = __popc(mk[u] & ((1u << lane) - 1u));
                list[off + rank] = base0 + u*32 + lane;
            }
            off += __popc(mk[u]);
        }
        __syncthreads();
    }

    // ---------------- Phase 4: segmented composite (4 segments x 64 pixels) --
    const int seg = tid >> 6;
    const int pix = tid & 63;
    const int lx = pix & 7;
    const int ly = pix >> 3;
    const float px = (float)(tx0 + lx) + 0.5f;
    const float py = (float)(ty0 + ly) + 0.5f;

    int count = wcnt[8];
    int slen = (count + 3) >> 2;
    int segstart = seg * slen;
    int segend = min(segstart + slen, count);

    float T = 1.0f;
    float cr = 0.0f, cg = 0.0f, cb = 0.0f;
    bool done = (segstart >= segend);
    int nch = (slen + 63) >> 6;

    for (int c0 = 0; c0 < nch; ++c0) {
        int base = segstart + (c0 << 6);
        int nb = min(64, segend - base);
        if (pix < nb) {
            int gi = list[base + pix];
            stageA[seg][pix] = g_sorted[gi*3];
            stageB[seg][pix] = g_sorted[gi*3 + 1];
            stageC[seg][pix] = ((const float*)g_sorted)[gi*12 + 8];
        }
        __syncthreads();

        if (!done) {
            for (int j = 0; j < nb; ++j) {
                float4 A = stageA[seg][j];
                float4 B = stageB[seg][j];
                float dx = px - A.x;
                float dy = py - A.y;
                float power = -0.5f * (A.z*dx*dx + B.x*dy*dy) - A.w*dx*dy;
                if (power <= 0.0f) {
                    float g = fminf(B.y * __expf(power), 0.99f);
                    if (g >= (1.0f/255.0f)) {
                        float w = T * g;
                        cr = fmaf(w, B.z, cr);
                        cg = fmaf(w, B.w, cg);
                        cb = fmaf(w, stageC[seg][j], cb);
                        T *= (1.0f - g);
                    }
                }
            }
            if (T < 1e-6f) done = true;
        }
        if (__syncthreads_count(done) == NTHREADS) break;
    }

    part[seg][pix] = make_float4(cr, cg, cb, T);
    __syncthreads();

    if (tid < 64) {
        float4 p0 = part[0][tid], p1 = part[1][tid], p2 = part[2][tid], p3 = part[3][tid];
        float ocr = p0.x + p0.w*(p1.x + p1.w*(p2.x + p2.w*p3.x));
        float ocg = p0.y + p0.w*(p1.y + p1.w*(p2.y + p2.w*p3.y));
        float ocb = p0.z + p0.w*(p1.z + p1.w*(p2.z + p2.w*p3.z));
        int x = tx0 + (tid & 7), y = ty0 + (tid >> 3);
        out[0*(IMW*IMH) + y*IMW + x] = ocr;
        out[1*(IMW*IMH) + y*IMW + x] = ocg;
        out[2*(IMW*IMH) + y*IMW + x] = ocb;
    }
}

extern "C" void kernel_launch(void* const* d_in, const int* in_sizes, int n_in,
                              void* d_out, int out_size)
{
    const float* pws        = (const float*)d_in[0];
    const float* shs        = (const float*)d_in[1];
    const float* alphas_raw = (const float*)d_in[2];
    const float* scales_raw = (const float*)d_in[3];
    const float* rots_raw   = (const float*)d_in[4];
    // d_in[5] = us (unused by the reference)
    const float* Rcw        = (const float*)d_in[6];
    const float* tcw        = (const float*)d_in[7];

    float* out = (float*)d_out;

    fused_kernel<<<NBLOCKS, NTHREADS>>>(pws, shs, alphas_raw, scales_raw,
                                        rots_raw, Rcw, tcw, out);
}

// round 6
// speedup vs baseline: 39.9015x; 1.1364x over previous
#include <cuda_runtime.h>
#include <cuda_bf16.h>
#include <math.h>

#define NG 2048
#define IMW 128
#define IMH 128
#define FX 400.0f
#define FY 400.0f
#define CX 64.0f
#define CY 64.0f
#define NBLOCKS 128        // one block per SM; each block owns 2 tiles (8x8)
#define NTHREADS 512       // 2 tiles x 4 depth-segments x 64 pixels

// packed per-gaussian record (3 float4):
//  [0]ux [1]uy [2]cinv0 [3]cinv1 | [4]cinv2 [5]alpha [6]r [7]g | [8]b [9]wx [10]wy [11]pad
__device__ float4 g_packed4[NG * 3];
__device__ float  g_depth[NG];
__device__ float4 g_sorted[NG * 3];   // sorted stream
__device__ float4 g_bbox[NG];         // sorted: ux, uy, wx, wy

__device__ unsigned bar_cnt = 0;
__device__ volatile unsigned bar_gen = 0;

__device__ __forceinline__ void grid_barrier()
{
    __syncthreads();
    if (threadIdx.x == 0) {
        unsigned gen = bar_gen;
        __threadfence();
        unsigned arrived = atomicAdd(&bar_cnt, 1u);
        if (arrived == gridDim.x - 1) {
            bar_cnt = 0;
            __threadfence();
            bar_gen = gen + 1;
        } else {
            while (bar_gen == gen) __nanosleep(32);
            __threadfence();
        }
    }
    __syncthreads();
}

__constant__ float kSH_C0 = 0.28209479177387814f;
__constant__ float kSH_C1 = 0.4886025119029199f;

__global__ void __launch_bounds__(NTHREADS) fused_kernel(
    const float* __restrict__ pws,
    const float* __restrict__ shs,
    const float* __restrict__ alphas_raw,
    const float* __restrict__ scales_raw,
    const float* __restrict__ rots_raw,
    const float* __restrict__ Rcw,
    const float* __restrict__ tcw,
    float* __restrict__ out)
{
    __shared__ int    list2[2][NG];   // per-tile lists (phase 3/4); low half doubles as depth buf
    __shared__ int    wcnt[2][9];
    __shared__ float4 stageA[8][64];
    __shared__ float4 stageB[8][64];
    __shared__ float  stageC[8][64];
    __shared__ float4 part[8][64];    // (r,g,b,T) per group per pixel

    float* sd = (float*)list2[0];     // NG floats, used only in phase 2

    const int tid = threadIdx.x;
    float* areas_out = out + 3 * IMW * IMH;

    // ---------------- Phase 1: preprocess (first 64 threads; 4 thr/gauss) ----
    if (tid < 64) {
        int unit = blockIdx.x * 64 + tid;    // 8192 units
        int i = unit >> 2;
        int q = unit & 3;

        float R00 = Rcw[0], R01 = Rcw[1], R02 = Rcw[2];
        float R10 = Rcw[3], R11 = Rcw[4], R12 = Rcw[5];
        float R20 = Rcw[6], R21 = Rcw[7], R22 = Rcw[8];
        float t0 = tcw[0], t1 = tcw[1], t2 = tcw[2];

        float pwx = pws[i*3+0], pwy = pws[i*3+1], pwz = pws[i*3+2];

        if (q < 3) {
            // color lane: channel q
            float twc0 = -(R00*t0 + R10*t1 + R20*t2);
            float twc1 = -(R01*t0 + R11*t1 + R21*t2);
            float twc2 = -(R02*t0 + R12*t1 + R22*t2);
            float dx = pwx - twc0, dy = pwy - twc1, dz = pwz - twc2;
            float dn = rsqrtf(dx*dx + dy*dy + dz*dz);
            float x = dx*dn, y = dy*dn, zd = dz*dn;

            float xx = x*x, yy = y*y, zz = zd*zd;
            float xy = x*y, yz = y*zd, xz = x*zd;

            float bs[16];
            bs[0]  = kSH_C0;
            bs[1]  = -kSH_C1 * y;
            bs[2]  =  kSH_C1 * zd;
            bs[3]  = -kSH_C1 * x;
            bs[4]  =  1.0925484305920792f  * xy;
            bs[5]  = -1.0925484305920792f  * yz;
            bs[6]  =  0.31539156525252005f * (2.0f*zz - xx - yy);
            bs[7]  = -1.0925484305920792f  * xz;
            bs[8]  =  0.5462742152960396f  * (xx - yy);
            bs[9]  = -0.5900435899266435f  * y * (3.0f*xx - yy);
            bs[10] =  2.890611442640554f   * xy * zd;
            bs[11] = -0.4570457994644658f  * y * (4.0f*zz - xx - yy);
            bs[12] =  0.3731763325901154f  * zd * (2.0f*zz - 3.0f*xx - 3.0f*yy);
            bs[13] = -0.4570457994644658f  * x * (4.0f*zz - xx - yy);
            bs[14] =  1.445305721320277f   * zd * (xx - yy);
            bs[15] = -0.5900435899266435f  * x * (xx - 3.0f*yy);

            const float* sh = shs + i*48 + q;
            float v[16];
            #pragma unroll
            for (int j = 0; j < 16; ++j) v[j] = __ldg(sh + j*3);
            float acc = 0.5f;
            #pragma unroll
            for (int j = 0; j < 16; ++j) acc = fmaf(bs[j], v[j], acc);
            ((float*)g_packed4)[i*12 + 6 + q] = fmaxf(acc, 0.0f);
        } else {
            // geometry lane
            float pc0 = R00*pwx + R01*pwy + R02*pwz + t0;
            float pc1 = R10*pwx + R11*pwy + R12*pwz + t1;
            float pc2 = R20*pwx + R21*pwy + R22*pwz + t2;

            float depth = pc2;
            bool valid = depth > 0.2f;
            float z = valid ? depth : 1.0f;
            float invz = __fdividef(1.0f, z);

            float ux = FX * pc0 * invz + CX;
            float uy = FY * pc1 * invz + CY;

            float qw = rots_raw[i*4+0], qx = rots_raw[i*4+1];
            float qy = rots_raw[i*4+2], qz = rots_raw[i*4+3];
            float qn = rsqrtf(qw*qw + qx*qx + qy*qy + qz*qz);
            qw *= qn; qx *= qn; qy *= qn; qz *= qn;

            float r00 = 1.0f - 2.0f*(qy*qy + qz*qz);
            float r01 = 2.0f*(qx*qy - qw*qz);
            float r02 = 2.0f*(qx*qz + qw*qy);
            float r10 = 2.0f*(qx*qy + qw*qz);
            float r11 = 1.0f - 2.0f*(qx*qx + qz*qz);
            float r12 = 2.0f*(qy*qz - qw*qx);
            float r20 = 2.0f*(qx*qz - qw*qy);
            float r21 = 2.0f*(qy*qz + qw*qx);
            float r22 = 1.0f - 2.0f*(qx*qx + qy*qy);

            float s0 = __expf(scales_raw[i*3+0]);
            float s1 = __expf(scales_raw[i*3+1]);
            float s2 = __expf(scales_raw[i*3+2]);

            float m00 = r00*s0, m01 = r01*s1, m02 = r02*s2;
            float m10 = r10*s0, m11 = r11*s1, m12 = r12*s2;
            float m20 = r20*s0, m21 = r21*s1, m22 = r22*s2;

            float Sxx = m00*m00 + m01*m01 + m02*m02;
            float Sxy = m00*m10 + m01*m11 + m02*m12;
            float Sxz = m00*m20 + m01*m21 + m02*m22;
            float Syy = m10*m10 + m11*m11 + m12*m12;
            float Syz = m10*m20 + m11*m21 + m12*m22;
            float Szz = m20*m20 + m21*m21 + m22*m22;

            const float limx = 1.3f * 0.5f * (float)IMW / FX;
            const float limy = 1.3f * 0.5f * (float)IMH / FY;
            float txl = fminf(fmaxf(pc0 * invz, -limx), limx) * z;
            float tyl = fminf(fmaxf(pc1 * invz, -limy), limy) * z;

            float j00 = FX * invz;
            float j02 = -FX * txl * invz * invz;
            float j11 = FY * invz;
            float j12 = -FY * tyl * invz * invz;

            float T00 = j00*R00 + j02*R20;
            float T01 = j00*R01 + j02*R21;
            float T02 = j00*R02 + j02*R22;
            float T10 = j11*R10 + j12*R20;
            float T11 = j11*R11 + j12*R21;
            float T12 = j11*R12 + j12*R22;

            float u0 = T00*Sxx + T01*Sxy + T02*Sxz;
            float u1 = T00*Sxy + T01*Syy + T02*Syz;
            float u2 = T00*Sxz + T01*Syz + T02*Szz;
            float v0 = T10*Sxx + T11*Sxy + T12*Sxz;
            float v1 = T10*Sxy + T11*Syy + T12*Syz;
            float v2 = T10*Sxz + T11*Syz + T12*Szz;

            float a = u0*T00 + u1*T01 + u2*T02 + 0.3f;
            float b = u0*T10 + u1*T11 + u2*T12;
            float c = v0*T10 + v1*T11 + v2*T12 + 0.3f;

            float det = a*c - b*b;
            valid = valid && (det > 0.0f);
            float inv_det = __fdividef(1.0f, valid ? det : 1.0f);
            float ci0 = c * inv_det;
            float ci1 = -b * inv_det;
            float ci2 = a * inv_det;

            float mid = 0.5f * (a + c);
            float disc = sqrtf(fmaxf(mid*mid - det, 0.1f));
            float ar0 = 3.0f * sqrtf(fmaxf(mid + disc, 0.0f));
            float ar1 = 3.0f * sqrtf(fmaxf(mid - disc, 0.0f));
            areas_out[2*i+0] = valid ? ar0 : 0.0f;
            areas_out[2*i+1] = valid ? ar1 : 0.0f;

            float alpha = __fdividef(1.0f, 1.0f + __expf(-alphas_raw[i]));
            float alpha_eff = valid ? alpha : 0.0f;

            float wx = -1.0f, wy = -1.0f;
            if (valid && alpha_eff >= (1.0f/255.0f)) {
                float tau = 2.0f * __logf(255.0f * alpha_eff);
                if (tau > 0.0f) {
                    wx = sqrtf(tau * a) + 0.05f;
                    wy = sqrtf(tau * c) + 0.05f;
                }
            }

            g_depth[i] = depth;
            float* p = (float*)(g_packed4 + i*3);
            p[0] = ux; p[1] = uy; p[2] = ci0; p[3] = ci1;
            p[4] = ci2; p[5] = alpha_eff;
            p[9] = wx; p[10] = wy; p[11] = 0.0f;
        }
    }

    grid_barrier();

    // ---------------- Phase 2: rank sort + scatter (1 warp / gaussian) -------
    {
        #pragma unroll
        for (int j = tid; j < NG; j += NTHREADS) sd[j] = g_depth[j];
        __syncthreads();

        int lane = tid & 31;
        int i = blockIdx.x * 16 + (tid >> 5);   // one gaussian per warp; 128*16 = 2048
        float d = sd[i];

        int r = 0;
        #pragma unroll 8
        for (int j = lane; j < NG; j += 32) {   // stride-32: conflict-free
            float dj = sd[j];
            r += (dj < d) || (dj == d && j < i);
        }
        #pragma unroll
        for (int o = 16; o > 0; o >>= 1) r += __shfl_xor_sync(0xffffffffu, r, o);

        if (lane < 3) {
            g_sorted[r*3 + lane] = g_packed4[i*3 + lane];
        } else if (lane == 3) {
            float4 A = g_packed4[i*3 + 0];
            float4 C = g_packed4[i*3 + 2];
            g_bbox[r] = make_float4(A.x, A.y, C.y, C.z);
        }
        __syncthreads();   // sd reuse (list2) happens after this phase
    }

    grid_barrier();

    // ---------------- Phase 3: binning — 2 tiles, 8 warps each ---------------
    // tiles 2*blockIdx.x + h, h in {0,1}; tile layout: 16x16 grid of 8x8 tiles
    const int tileBase = blockIdx.x * 2;
    {
        int w = tid >> 5, lane = tid & 31;
        int h = w >> 3;                 // tile half
        int wl = w & 7;
        int tile = tileBase + h;
        int tx0 = (tile & 15) * 8;
        int ty0 = (tile >> 4) * 8;
        float bx0 = (float)tx0 + 0.5f, bx1 = (float)tx0 + 7.5f;
        float by0 = (float)ty0 + 0.5f, by1 = (float)ty0 + 7.5f;

        int base0 = wl * (NG / 8);
        float4 bb[8];
        unsigned mk[8];
        #pragma unroll
        for (int u = 0; u < 8; ++u) bb[u] = g_bbox[base0 + u*32 + lane];
        int cnt = 0;
        #pragma unroll
        for (int u = 0; u < 8; ++u) {
            bool hit = (bb[u].z > 0.0f) &&
                       (bb[u].x - bb[u].z <= bx1) && (bb[u].x + bb[u].z >= bx0) &&
                       (bb[u].y - bb[u].w <= by1) && (bb[u].y + bb[u].w >= by0);
            mk[u] = __ballot_sync(0xffffffffu, hit);
            cnt += __popc(mk[u]);
        }
        if (lane == 0) wcnt[h][wl] = cnt;
        __syncthreads();
        if (tid < 2) {
            int acc = 0;
            #pragma unroll
            for (int w2 = 0; w2 < 8; ++w2) { int t = wcnt[tid][w2]; wcnt[tid][w2] = acc; acc += t; }
            wcnt[tid][8] = acc;
        }
        __syncthreads();
        int off = wcnt[h][wl];
        #pragma unroll
        for (int u = 0; u < 8; ++u) {
            if ((mk[u] >> lane) & 1u) {
                int rank = __popc(mk[u] & ((1u << lane) - 1u));
                list2[h][off + rank] = base0 + u*32 + lane;
            }
            off += __popc(mk[u]);
        }
        __syncthreads();
    }

    // ---------------- Phase 4: composite — 8 groups (2 tiles x 4 segments) ---
    const int grp = tid >> 6;          // 0..7
    const int h   = grp >> 2;          // tile half
    const int seg = grp & 3;
    const int pix = tid & 63;
    const int tile = tileBase + h;
    const int tx0 = (tile & 15) * 8;
    const int ty0 = (tile >> 4) * 8;
    const int lx = pix & 7;
    const int ly = pix >> 3;
    const float px = (float)(tx0 + lx) + 0.5f;
    const float py = (float)(ty0 + ly) + 0.5f;

    int count = wcnt[h][8];
    int slen = (count + 3) >> 2;
    int segstart = seg * slen;
    int segend = min(segstart + slen, count);

    // uniform chunk count across both tiles (block-wide syncs inside loop)
    int c0a = wcnt[0][8], c0b = wcnt[1][8];
    int nchmax = (max((c0a + 3) >> 2, (c0b + 3) >> 2) + 63) >> 6;

    float T = 1.0f;
    float cr = 0.0f, cg = 0.0f, cb = 0.0f;
    bool done = (segstart >= segend);

    for (int c0 = 0; c0 < nchmax; ++c0) {
        int base = segstart + (c0 << 6);
        int nb = min(64, segend - base);
        if (pix < nb) {
            int gi = list2[h][base + pix];
            stageA[grp][pix] = g_sorted[gi*3];
            stageB[grp][pix] = g_sorted[gi*3 + 1];
            stageC[grp][pix] = ((const float*)g_sorted)[gi*12 + 8];
        }
        __syncthreads();

        if (!done && nb > 0) {
            for (int j = 0; j < nb; ++j) {
                float4 A = stageA[grp][j];
                float4 B = stageB[grp][j];
                float dx = px - A.x;
                float dy = py - A.y;
                float power = -0.5f * (A.z*dx*dx + B.x*dy*dy) - A.w*dx*dy;
                if (power <= 0.0f) {
                    float g = fminf(B.y * __expf(power), 0.99f);
                    if (g >= (1.0f/255.0f)) {
                        float w = T * g;
                        cr = fmaf(w, B.z, cr);
                        cg = fmaf(w, B.w, cg);
                        cb = fmaf(w, stageC[grp][j], cb);
                        T *= (1.0f - g);
                    }
                }
            }
            if (T < 1e-6f) done = true;
        }
        if (__syncthreads_count(done) == NTHREADS) break;
    }

    part[grp][pix] = make_float4(cr, cg, cb, T);
    __syncthreads();

    if (tid < 128) {
        int hh = tid >> 6;             // tile half
        int p2 = tid & 63;
        float4 p0 = part[hh*4+0][p2], p1 = part[hh*4+1][p2];
        float4 q2 = part[hh*4+2][p2], q3 = part[hh*4+3][p2];
        float ocr = p0.x + p0.w*(p1.x + p1.w*(q2.x + q2.w*q3.x));
        float ocg = p0.y + p0.w*(p1.y + p1.w*(q2.y + q2.w*q3.y));
        float ocb = p0.z + p0.w*(p1.z + p1.w*(q2.z + q2.w*q3.z));
        int tl = tileBase + hh;
        int x = (tl & 15) * 8 + (p2 & 7);
        int y = (tl >> 4) * 8 + (p2 >> 3);
        out[0*(IMW*IMH) + y*IMW + x] = ocr;
        out[1*(IMW*IMH) + y*IMW + x] = ocg;
        out[2*(IMW*IMH) + y*IMW + x] = ocb;
    }
}

extern "C" void kernel_launch(void* const* d_in, const int* in_sizes, int n_in,
                              void* d_out, int out_size)
{
    const float* pws        = (const float*)d_in[0];
    const float* shs        = (const float*)d_in[1];
    const float* alphas_raw = (const float*)d_in[2];
    const float* scales_raw = (const float*)d_in[3];
    const float* rots_raw   = (const float*)d_in[4];
    // d_in[5] = us (unused by the reference)
    const float* Rcw        = (const float*)d_in[6];
    const float* tcw        = (const float*)d_in[7];

    float* out = (float*)d_out;

    fused_kernel<<<NBLOCKS, NTHREADS>>>(pws, shs, alphas_raw, scales_raw,
                                        rots_raw, Rcw, tcw, out);
}

// round 7
// speedup vs baseline: 39.9772x; 1.0019x over previous
#include <cuda_runtime.h>
#include <cuda_bf16.h>
#include <math.h>

#define NG 2048
#define IMW 128
#define IMH 128
#define FX 400.0f
#define FY 400.0f
#define CX 64.0f
#define CY 64.0f
#define NBLOCKS 128        // one block per SM; each block owns 2 tiles (8x8)
#define NTHREADS 1024      // 2 tiles x 8 depth-segments x 64 pixels

// packed per-gaussian record (3 float4):
//  [0]ux [1]uy [2]cinv0 [3]cinv1 | [4]cinv2 [5]alpha [6]r [7]g | [8]b [9]wx [10]wy [11]pad
__device__ float4 g_packed4[NG * 3];
__device__ float  g_depth[NG];
__device__ float4 g_sorted[NG * 3];   // sorted stream
__device__ float4 g_bbox[NG];         // sorted: ux, uy, wx, wy

__device__ unsigned bar_cnt = 0;
__device__ volatile unsigned bar_gen = 0;

__device__ __forceinline__ void grid_barrier()
{
    __syncthreads();
    if (threadIdx.x == 0) {
        unsigned gen = bar_gen;
        __threadfence();
        unsigned arrived = atomicAdd(&bar_cnt, 1u);
        if (arrived == gridDim.x - 1) {
            bar_cnt = 0;
            __threadfence();
            bar_gen = gen + 1;
        } else {
            while (bar_gen == gen) __nanosleep(32);
            __threadfence();
        }
    }
    __syncthreads();
}

__constant__ float kSH_C0 = 0.28209479177387814f;
__constant__ float kSH_C1 = 0.4886025119029199f;

__global__ void __launch_bounds__(NTHREADS) fused_kernel(
    const float* __restrict__ pws,
    const float* __restrict__ shs,
    const float* __restrict__ alphas_raw,
    const float* __restrict__ scales_raw,
    const float* __restrict__ rots_raw,
    const float* __restrict__ Rcw,
    const float* __restrict__ tcw,
    float* __restrict__ out)
{
    __shared__ int    list2[2][NG];   // 16KB: tile lists; reused for depths (ph2) & partials (ph4 end)
    __shared__ int    wcnt[2][17];
    __shared__ int    prank[32];
    __shared__ float4 stageA[16][32];
    __shared__ float4 stageB[16][32];
    __shared__ float  stageC[16][32];

    float* sd = (float*)list2[0];     // NG floats, phase 2 only

    const int tid = threadIdx.x;
    float* areas_out = out + 3 * IMW * IMH;

    // ---------------- Phase 1: preprocess (first 64 threads; 4 thr/gauss) ----
    if (tid < 64) {
        int unit = blockIdx.x * 64 + tid;    // 8192 units
        int i = unit >> 2;
        int q = unit & 3;

        float R00 = Rcw[0], R01 = Rcw[1], R02 = Rcw[2];
        float R10 = Rcw[3], R11 = Rcw[4], R12 = Rcw[5];
        float R20 = Rcw[6], R21 = Rcw[7], R22 = Rcw[8];
        float t0 = tcw[0], t1 = tcw[1], t2 = tcw[2];

        float pwx = pws[i*3+0], pwy = pws[i*3+1], pwz = pws[i*3+2];

        if (q < 3) {
            // color lane: channel q
            float twc0 = -(R00*t0 + R10*t1 + R20*t2);
            float twc1 = -(R01*t0 + R11*t1 + R21*t2);
            float twc2 = -(R02*t0 + R12*t1 + R22*t2);
            float dx = pwx - twc0, dy = pwy - twc1, dz = pwz - twc2;
            float dn = rsqrtf(dx*dx + dy*dy + dz*dz);
            float x = dx*dn, y = dy*dn, zd = dz*dn;

            float xx = x*x, yy = y*y, zz = zd*zd;
            float xy = x*y, yz = y*zd, xz = x*zd;

            float bs[16];
            bs[0]  = kSH_C0;
            bs[1]  = -kSH_C1 * y;
            bs[2]  =  kSH_C1 * zd;
            bs[3]  = -kSH_C1 * x;
            bs[4]  =  1.0925484305920792f  * xy;
            bs[5]  = -1.0925484305920792f  * yz;
            bs[6]  =  0.31539156525252005f * (2.0f*zz - xx - yy);
            bs[7]  = -1.0925484305920792f  * xz;
            bs[8]  =  0.5462742152960396f  * (xx - yy);
            bs[9]  = -0.5900435899266435f  * y * (3.0f*xx - yy);
            bs[10] =  2.890611442640554f   * xy * zd;
            bs[11] = -0.4570457994644658f  * y * (4.0f*zz - xx - yy);
            bs[12] =  0.3731763325901154f  * zd * (2.0f*zz - 3.0f*xx - 3.0f*yy);
            bs[13] = -0.4570457994644658f  * x * (4.0f*zz - xx - yy);
            bs[14] =  1.445305721320277f   * zd * (xx - yy);
            bs[15] = -0.5900435899266435f  * x * (xx - 3.0f*yy);

            const float* sh = shs + i*48 + q;
            float v[16];
            #pragma unroll
            for (int j = 0; j < 16; ++j) v[j] = __ldg(sh + j*3);
            float acc = 0.5f;
            #pragma unroll
            for (int j = 0; j < 16; ++j) acc = fmaf(bs[j], v[j], acc);
            ((float*)g_packed4)[i*12 + 6 + q] = fmaxf(acc, 0.0f);
        } else {
            // geometry lane
            float pc0 = R00*pwx + R01*pwy + R02*pwz + t0;
            float pc1 = R10*pwx + R11*pwy + R12*pwz + t1;
            float pc2 = R20*pwx + R21*pwy + R22*pwz + t2;

            float depth = pc2;
            bool valid = depth > 0.2f;
            float z = valid ? depth : 1.0f;
            float invz = __fdividef(1.0f, z);

            float ux = FX * pc0 * invz + CX;
            float uy = FY * pc1 * invz + CY;

            float qw = rots_raw[i*4+0], qx = rots_raw[i*4+1];
            float qy = rots_raw[i*4+2], qz = rots_raw[i*4+3];
            float qn = rsqrtf(qw*qw + qx*qx + qy*qy + qz*qz);
            qw *= qn; qx *= qn; qy *= qn; qz *= qn;

            float r00 = 1.0f - 2.0f*(qy*qy + qz*qz);
            float r01 = 2.0f*(qx*qy - qw*qz);
            float r02 = 2.0f*(qx*qz + qw*qy);
            float r10 = 2.0f*(qx*qy + qw*qz);
            float r11 = 1.0f - 2.0f*(qx*qx + qz*qz);
            float r12 = 2.0f*(qy*qz - qw*qx);
            float r20 = 2.0f*(qx*qz - qw*qy);
            float r21 = 2.0f*(qy*qz + qw*qx);
            float r22 = 1.0f - 2.0f*(qx*qx + qy*qy);

            float s0 = __expf(scales_raw[i*3+0]);
            float s1 = __expf(scales_raw[i*3+1]);
            float s2 = __expf(scales_raw[i*3+2]);

            float m00 = r00*s0, m01 = r01*s1, m02 = r02*s2;
            float m10 = r10*s0, m11 = r11*s1, m12 = r12*s2;
            float m20 = r20*s0, m21 = r21*s1, m22 = r22*s2;

            float Sxx = m00*m00 + m01*m01 + m02*m02;
            float Sxy = m00*m10 + m01*m11 + m02*m12;
            float Sxz = m00*m20 + m01*m21 + m02*m22;
            float Syy = m10*m10 + m11*m11 + m12*m12;
            float Syz = m10*m20 + m11*m21 + m12*m22;
            float Szz = m20*m20 + m21*m21 + m22*m22;

            const float limx = 1.3f * 0.5f * (float)IMW / FX;
            const float limy = 1.3f * 0.5f * (float)IMH / FY;
            float txl = fminf(fmaxf(pc0 * invz, -limx), limx) * z;
            float tyl = fminf(fmaxf(pc1 * invz, -limy), limy) * z;

            float j00 = FX * invz;
            float j02 = -FX * txl * invz * invz;
            float j11 = FY * invz;
            float j12 = -FY * tyl * invz * invz;

            float T00 = j00*R00 + j02*R20;
            float T01 = j00*R01 + j02*R21;
            float T02 = j00*R02 + j02*R22;
            float T10 = j11*R10 + j12*R20;
            float T11 = j11*R11 + j12*R21;
            float T12 = j11*R12 + j12*R22;

            float u0 = T00*Sxx + T01*Sxy + T02*Sxz;
            float u1 = T00*Sxy + T01*Syy + T02*Syz;
            float u2 = T00*Sxz + T01*Syz + T02*Szz;
            float v0 = T10*Sxx + T11*Sxy + T12*Sxz;
            float v1 = T10*Sxy + T11*Syy + T12*Syz;
            float v2 = T10*Sxz + T11*Syz + T12*Szz;

            float a = u0*T00 + u1*T01 + u2*T02 + 0.3f;
            float b = u0*T10 + u1*T11 + u2*T12;
            float c = v0*T10 + v1*T11 + v2*T12 + 0.3f;

            float det = a*c - b*b;
            valid = valid && (det > 0.0f);
            float inv_det = __fdividef(1.0f, valid ? det : 1.0f);
            float ci0 = c * inv_det;
            float ci1 = -b * inv_det;
            float ci2 = a * inv_det;

            float mid = 0.5f * (a + c);
            float disc = sqrtf(fmaxf(mid*mid - det, 0.1f));
            float ar0 = 3.0f * sqrtf(fmaxf(mid + disc, 0.0f));
            float ar1 = 3.0f * sqrtf(fmaxf(mid - disc, 0.0f));
            areas_out[2*i+0] = valid ? ar0 : 0.0f;
            areas_out[2*i+1] = valid ? ar1 : 0.0f;

            float alpha = __fdividef(1.0f, 1.0f + __expf(-alphas_raw[i]));
            float alpha_eff = valid ? alpha : 0.0f;

            float wx = -1.0f, wy = -1.0f;
            if (valid && alpha_eff >= (1.0f/255.0f)) {
                float tau = 2.0f * __logf(255.0f * alpha_eff);
                if (tau > 0.0f) {
                    wx = sqrtf(tau * a) + 0.05f;
                    wy = sqrtf(tau * c) + 0.05f;
                }
            }

            g_depth[i] = depth;
            float* p = (float*)(g_packed4 + i*3);
            p[0] = ux; p[1] = uy; p[2] = ci0; p[3] = ci1;
            p[4] = ci2; p[5] = alpha_eff;
            p[9] = wx; p[10] = wy; p[11] = 0.0f;
        }
    }

    grid_barrier();

    // ---------------- Phase 2: rank sort + scatter (2 warps / gaussian) ------
    {
        #pragma unroll
        for (int j = tid; j < NG; j += NTHREADS) sd[j] = g_depth[j];
        __syncthreads();

        int w = tid >> 5;
        int lane = tid & 31;
        int pair = w >> 1;                       // 0..15
        int half = w & 1;
        int i = blockIdx.x * 16 + pair;          // 128*16 = 2048
        float d = sd[i];

        int r = 0;
        int j0 = half * 32 + lane;
        #pragma unroll 8
        for (int j = j0; j < NG; j += 64) {      // 32 iters, conflict-free
            float dj = sd[j];
            r += (dj < d) || (dj == d && j < i);
        }
        #pragma unroll
        for (int o = 16; o > 0; o >>= 1) r += __shfl_xor_sync(0xffffffffu, r, o);
        if (lane == 0) prank[w] = r;
        __syncthreads();

        if (half == 0) {
            int rt = prank[2*pair] + prank[2*pair + 1];
            if (lane < 3) {
                g_sorted[rt*3 + lane] = g_packed4[i*3 + lane];
            } else if (lane == 3) {
                float4 A = g_packed4[i*3 + 0];
                float4 C = g_packed4[i*3 + 2];
                g_bbox[rt] = make_float4(A.x, A.y, C.y, C.z);
            }
        }
        __syncthreads();   // sd (list2) reused in phase 3
    }

    grid_barrier();

    // ---------------- Phase 3: binning — 2 tiles, 16 warps each --------------
    const int tileBase = blockIdx.x * 2;
    {
        int w = tid >> 5, lane = tid & 31;
        int h = w >> 4;                 // tile half
        int wl = w & 15;
        int tile = tileBase + h;
        int tx0 = (tile & 15) * 8;
        int ty0 = (tile >> 4) * 8;
        float bx0 = (float)tx0 + 0.5f, bx1 = (float)tx0 + 7.5f;
        float by0 = (float)ty0 + 0.5f, by1 = (float)ty0 + 7.5f;

        int base0 = wl * (NG / 16);     // 128 gaussians per warp
        float4 bb[4];
        unsigned mk[4];
        #pragma unroll
        for (int u = 0; u < 4; ++u) bb[u] = g_bbox[base0 + u*32 + lane];
        int cnt = 0;
        #pragma unroll
        for (int u = 0; u < 4; ++u) {
            bool hit = (bb[u].z > 0.0f) &&
                       (bb[u].x - bb[u].z <= bx1) && (bb[u].x + bb[u].z >= bx0) &&
                       (bb[u].y - bb[u].w <= by1) && (bb[u].y + bb[u].w >= by0);
            mk[u] = __ballot_sync(0xffffffffu, hit);
            cnt += __popc(mk[u]);
        }
        if (lane == 0) wcnt[h][wl] = cnt;
        __syncthreads();
        if (tid < 2) {
            int acc = 0;
            #pragma unroll
            for (int w2 = 0; w2 < 16; ++w2) { int t = wcnt[tid][w2]; wcnt[tid][w2] = acc; acc += t; }
            wcnt[tid][16] = acc;
        }
        __syncthreads();
        int off = wcnt[h][wl];
        #pragma unroll
        for (int u = 0; u < 4; ++u) {
            if ((mk[u] >> lane) & 1u) {
                int rank = __popc(mk[u] & ((1u << lane) - 1u));
                list2[h][off + rank] = base0 + u*32 + lane;
            }
            off += __popc(mk[u]);
        }
        __syncthreads();
    }

    // ---------------- Phase 4: composite — 16 groups (2 tiles x 8 segments) --
    const int grp = tid >> 6;          // 0..15
    const int h   = grp >> 3;          // tile half
    const int seg = grp & 7;
    const int pix = tid & 63;
    const int tile = tileBase + h;
    const int tx0 = (tile & 15) * 8;
    const int ty0 = (tile >> 4) * 8;
    const float px = (float)(tx0 + (pix & 7)) + 0.5f;
    const float py = (float)(ty0 + (pix >> 3)) + 0.5f;

    int count = wcnt[h][16];
    int slen = (count + 7) >> 3;
    int segstart = seg * slen;
    int segend = min(segstart + slen, count);

    // uniform chunk count across both tiles (block-wide syncs inside loop)
    int sl0 = (wcnt[0][16] + 7) >> 3, sl1 = (wcnt[1][16] + 7) >> 3;
    int nchmax = (max(sl0, sl1) + 31) >> 5;

    float T = 1.0f;
    float cr = 0.0f, cg = 0.0f, cb = 0.0f;
    bool done = (segstart >= segend);

    for (int c0 = 0; c0 < nchmax; ++c0) {
        int base = segstart + (c0 << 5);
        int nb = min(32, segend - base);
        if (pix < nb) {
            int gi = list2[h][base + pix];
            stageA[grp][pix] = g_sorted[gi*3];
            stageB[grp][pix] = g_sorted[gi*3 + 1];
            stageC[grp][pix] = ((const float*)g_sorted)[gi*12 + 8];
        }
        __syncthreads();

        if (!done && nb > 0) {
            for (int j = 0; j < nb; ++j) {
                float4 A = stageA[grp][j];
                float4 B = stageB[grp][j];
                float dx = px - A.x;
                float dy = py - A.y;
                float power = -0.5f * (A.z*dx*dx + B.x*dy*dy) - A.w*dx*dy;
                if (power <= 0.0f) {
                    float g = fminf(B.y * __expf(power), 0.99f);
                    if (g >= (1.0f/255.0f)) {
                        float w = T * g;
                        cr = fmaf(w, B.z, cr);
                        cg = fmaf(w, B.w, cg);
                        cb = fmaf(w, stageC[grp][j], cb);
                        T *= (1.0f - g);
                    }
                }
            }
            if (T < 1e-6f) done = true;
        }
        if (__syncthreads_count(done) == NTHREADS) break;
    }

    // loop exit is block-uniform -> safe to reuse list2 region for partials
    __syncthreads();
    float4* part = (float4*)list2;     // 16 groups x 64 px = 16KB
    part[grp*64 + pix] = make_float4(cr, cg, cb, T);
    __syncthreads();

    if (tid < 128) {
        int hh = tid >> 6;             // tile half
        int p2 = tid & 63;
        float4 acc = part[(hh*8 + 0)*64 + p2];
        #pragma unroll
        for (int s2 = 1; s2 < 8; ++s2) {
            float4 q = part[(hh*8 + s2)*64 + p2];
            acc.x = fmaf(acc.w, q.x, acc.x);
            acc.y = fmaf(acc.w, q.y, acc.y);
            acc.z = fmaf(acc.w, q.z, acc.z);
            acc.w *= q.w;
        }
        int tl = tileBase + hh;
        int x = (tl & 15) * 8 + (p2 & 7);
        int y = (tl >> 4) * 8 + (p2 >> 3);
        out[0*(IMW*IMH) + y*IMW + x] = acc.x;
        out[1*(IMW*IMH) + y*IMW + x] = acc.y;
        out[2*(IMW*IMH) + y*IMW + x] = acc.z;
    }
}

extern "C" void kernel_launch(void* const* d_in, const int* in_sizes, int n_in,
                              void* d_out, int out_size)
{
    const float* pws        = (const float*)d_in[0];
    const float* shs        = (const float*)d_in[1];
    const float* alphas_raw = (const float*)d_in[2];
    const float* scales_raw = (const float*)d_in[3];
    const float* rots_raw   = (const float*)d_in[4];
    // d_in[5] = us (unused by the reference)
    const float* Rcw        = (const float*)d_in[6];
    const float* tcw        = (const float*)d_in[7];

    float* out = (float*)d_out;

    fused_kernel<<<NBLOCKS, NTHREADS>>>(pws, shs, alphas_raw, scales_raw,
                                        rots_raw, Rcw, tcw, out);
}

// round 8
// speedup vs baseline: 43.8004x; 1.0956x over previous
#include <cuda_runtime.h>
#include <cuda_bf16.h>
#include <math.h>

#define NG 2048
#define IMW 128
#define IMH 128
#define FX 400.0f
#define FY 400.0f
#define CX 64.0f
#define CY 64.0f
#define NBLOCKS 128        // one block per SM; each block owns 2 tiles (8x8)
#define NTHREADS 1024

// unsorted per-gaussian record (3 float4):
//  [0]ux [1]uy [2]cinv0 [3]cinv1 | [4]cinv2 [5]alpha [6]r [7]g | [8]b ...
__device__ float4 g_packed4[NG * 3];
__device__ float  g_depth[NG];
__device__ float4 g_bbox[NG];         // unsorted: ux, uy, wx, wy

__device__ unsigned bar_cnt = 0;
__device__ volatile unsigned bar_gen = 0;

__device__ __forceinline__ void grid_barrier()
{
    __syncthreads();
    if (threadIdx.x == 0) {
        unsigned gen = bar_gen;
        __threadfence();
        unsigned arrived = atomicAdd(&bar_cnt, 1u);
        if (arrived == gridDim.x - 1) {
            bar_cnt = 0;
            __threadfence();
            bar_gen = gen + 1;
        } else {
            while (bar_gen == gen) __nanosleep(32);
            __threadfence();
        }
    }
    __syncthreads();
}

__constant__ float kSH_C0 = 0.28209479177387814f;
__constant__ float kSH_C1 = 0.4886025119029199f;

// dynamic smem: sidx[2][2048] | sdep[2][2048] | sord[2][2048] | part[16][64]
#define SMEM_DYN (2*NG*4*3 + 16*64*16)

__global__ void __launch_bounds__(NTHREADS, 1) fused_kernel(
    const float* __restrict__ pws,
    const float* __restrict__ shs,
    const float* __restrict__ alphas_raw,
    const float* __restrict__ scales_raw,
    const float* __restrict__ rots_raw,
    const float* __restrict__ Rcw,
    const float* __restrict__ tcw,
    float* __restrict__ out)
{
    extern __shared__ char smem_raw[];
    int*    sidx = (int*)smem_raw;                        // [2][NG]
    float*  sdep = (float*)(smem_raw + 2*NG*4);           // [2][NG]
    int*    sord = (int*)(smem_raw + 4*NG*4);             // [2][NG]
    float4* part = (float4*)(smem_raw + 6*NG*4);          // [16][64]

    __shared__ int wcnt[2][17];

    const int tid = threadIdx.x;
    float* areas_out = out + 3 * IMW * IMH;

    // ---------------- Phase 1: preprocess (first 64 threads; 4 thr/gauss) ----
    if (tid < 64) {
        int unit = blockIdx.x * 64 + tid;    // 8192 units
        int i = unit >> 2;
        int q = unit & 3;

        float R00 = Rcw[0], R01 = Rcw[1], R02 = Rcw[2];
        float R10 = Rcw[3], R11 = Rcw[4], R12 = Rcw[5];
        float R20 = Rcw[6], R21 = Rcw[7], R22 = Rcw[8];
        float t0 = tcw[0], t1 = tcw[1], t2 = tcw[2];

        float pwx = pws[i*3+0], pwy = pws[i*3+1], pwz = pws[i*3+2];

        if (q < 3) {
            // color lane: channel q
            float twc0 = -(R00*t0 + R10*t1 + R20*t2);
            float twc1 = -(R01*t0 + R11*t1 + R21*t2);
            float twc2 = -(R02*t0 + R12*t1 + R22*t2);
            float dx = pwx - twc0, dy = pwy - twc1, dz = pwz - twc2;
            float dn = rsqrtf(dx*dx + dy*dy + dz*dz);
            float x = dx*dn, y = dy*dn, zd = dz*dn;

            float xx = x*x, yy = y*y, zz = zd*zd;
            float xy = x*y, yz = y*zd, xz = x*zd;

            float bs[16];
            bs[0]  = kSH_C0;
            bs[1]  = -kSH_C1 * y;
            bs[2]  =  kSH_C1 * zd;
            bs[3]  = -kSH_C1 * x;
            bs[4]  =  1.0925484305920792f  * xy;
            bs[5]  = -1.0925484305920792f  * yz;
            bs[6]  =  0.31539156525252005f * (2.0f*zz - xx - yy);
            bs[7]  = -1.0925484305920792f  * xz;
            bs[8]  =  0.5462742152960396f  * (xx - yy);
            bs[9]  = -0.5900435899266435f  * y * (3.0f*xx - yy);
            bs[10] =  2.890611442640554f   * xy * zd;
            bs[11] = -0.4570457994644658f  * y * (4.0f*zz - xx - yy);
            bs[12] =  0.3731763325901154f  * zd * (2.0f*zz - 3.0f*xx - 3.0f*yy);
            bs[13] = -0.4570457994644658f  * x * (4.0f*zz - xx - yy);
            bs[14] =  1.445305721320277f   * zd * (xx - yy);
            bs[15] = -0.5900435899266435f  * x * (xx - 3.0f*yy);

            const float* sh = shs + i*48 + q;
            float v[16];
            #pragma unroll
            for (int j = 0; j < 16; ++j) v[j] = __ldg(sh + j*3);
            float acc = 0.5f;
            #pragma unroll
            for (int j = 0; j < 16; ++j) acc = fmaf(bs[j], v[j], acc);
            ((float*)g_packed4)[i*12 + 6 + q] = fmaxf(acc, 0.0f);
        } else {
            // geometry lane
            float pc0 = R00*pwx + R01*pwy + R02*pwz + t0;
            float pc1 = R10*pwx + R11*pwy + R12*pwz + t1;
            float pc2 = R20*pwx + R21*pwy + R22*pwz + t2;

            float depth = pc2;
            bool valid = depth > 0.2f;
            float z = valid ? depth : 1.0f;
            float invz = __fdividef(1.0f, z);

            float ux = FX * pc0 * invz + CX;
            float uy = FY * pc1 * invz + CY;

            float qw = rots_raw[i*4+0], qx = rots_raw[i*4+1];
            float qy = rots_raw[i*4+2], qz = rots_raw[i*4+3];
            float qn = rsqrtf(qw*qw + qx*qx + qy*qy + qz*qz);
            qw *= qn; qx *= qn; qy *= qn; qz *= qn;

            float r00 = 1.0f - 2.0f*(qy*qy + qz*qz);
            float r01 = 2.0f*(qx*qy - qw*qz);
            float r02 = 2.0f*(qx*qz + qw*qy);
            float r10 = 2.0f*(qx*qy + qw*qz);
            float r11 = 1.0f - 2.0f*(qx*qx + qz*qz);
            float r12 = 2.0f*(qy*qz - qw*qx);
            float r20 = 2.0f*(qx*qz - qw*qy);
            float r21 = 2.0f*(qy*qz + qw*qx);
            float r22 = 1.0f - 2.0f*(qx*qx + qy*qy);

            float s0 = __expf(scales_raw[i*3+0]);
            float s1 = __expf(scales_raw[i*3+1]);
            float s2 = __expf(scales_raw[i*3+2]);

            float m00 = r00*s0, m01 = r01*s1, m02 = r02*s2;
            float m10 = r10*s0, m11 = r11*s1, m12 = r12*s2;
            float m20 = r20*s0, m21 = r21*s1, m22 = r22*s2;

            float Sxx = m00*m00 + m01*m01 + m02*m02;
            float Sxy = m00*m10 + m01*m11 + m02*m12;
            float Sxz = m00*m20 + m01*m21 + m02*m22;
            float Syy = m10*m10 + m11*m11 + m12*m12;
            float Syz = m10*m20 + m11*m21 + m12*m22;
            float Szz = m20*m20 + m21*m21 + m22*m22;

            const float limx = 1.3f * 0.5f * (float)IMW / FX;
            const float limy = 1.3f * 0.5f * (float)IMH / FY;
            float txl = fminf(fmaxf(pc0 * invz, -limx), limx) * z;
            float tyl = fminf(fmaxf(pc1 * invz, -limy), limy) * z;

            float j00 = FX * invz;
            float j02 = -FX * txl * invz * invz;
            float j11 = FY * invz;
            float j12 = -FY * tyl * invz * invz;

            float T00 = j00*R00 + j02*R20;
            float T01 = j00*R01 + j02*R21;
            float T02 = j00*R02 + j02*R22;
            float T10 = j11*R10 + j12*R20;
            float T11 = j11*R11 + j12*R21;
            float T12 = j11*R12 + j12*R22;

            float u0 = T00*Sxx + T01*Sxy + T02*Sxz;
            float u1 = T00*Sxy + T01*Syy + T02*Syz;
            float u2 = T00*Sxz + T01*Syz + T02*Szz;
            float v0 = T10*Sxx + T11*Sxy + T12*Sxz;
            float v1 = T10*Sxy + T11*Syy + T12*Syz;
            float v2 = T10*Sxz + T11*Syz + T12*Szz;

            float a = u0*T00 + u1*T01 + u2*T02 + 0.3f;
            float b = u0*T10 + u1*T11 + u2*T12;
            float c = v0*T10 + v1*T11 + v2*T12 + 0.3f;

            float det = a*c - b*b;
            valid = valid && (det > 0.0f);
            float inv_det = __fdividef(1.0f, valid ? det : 1.0f);
            float ci0 = c * inv_det;
            float ci1 = -b * inv_det;
            float ci2 = a * inv_det;

            float mid = 0.5f * (a + c);
            float disc = sqrtf(fmaxf(mid*mid - det, 0.1f));
            float ar0 = 3.0f * sqrtf(fmaxf(mid + disc, 0.0f));
            float ar1 = 3.0f * sqrtf(fmaxf(mid - disc, 0.0f));
            areas_out[2*i+0] = valid ? ar0 : 0.0f;
            areas_out[2*i+1] = valid ? ar1 : 0.0f;

            float alpha = __fdividef(1.0f, 1.0f + __expf(-alphas_raw[i]));
            float alpha_eff = valid ? alpha : 0.0f;

            float wx = -1.0f, wy = -1.0f;
            if (valid && alpha_eff >= (1.0f/255.0f)) {
                float tau = 2.0f * __logf(255.0f * alpha_eff);
                if (tau > 0.0f) {
                    wx = sqrtf(tau * a) + 0.05f;
                    wy = sqrtf(tau * c) + 0.05f;
                }
            }

            g_depth[i] = depth;
            float* p = (float*)(g_packed4 + i*3);
            p[0] = ux; p[1] = uy; p[2] = ci0; p[3] = ci1;
            p[4] = ci2; p[5] = alpha_eff;
            g_bbox[i] = make_float4(ux, uy, wx, wy);
        }
    }

    grid_barrier();

    // ---------------- Phase 2: binning (unsorted) — 2 tiles, 16 warps each ---
    const int tileBase = blockIdx.x * 2;
    {
        int w = tid >> 5, lane = tid & 31;
        int h = w >> 4;                 // tile half
        int wl = w & 15;
        int tile = tileBase + h;
        int tx0 = (tile & 15) * 8;
        int ty0 = (tile >> 4) * 8;
        float bx0 = (float)tx0 + 0.5f, bx1 = (float)tx0 + 7.5f;
        float by0 = (float)ty0 + 0.5f, by1 = (float)ty0 + 7.5f;

        int base0 = wl * (NG / 16);     // 128 gaussians per warp
        float4 bb[4];
        unsigned mk[4];
        #pragma unroll
        for (int u = 0; u < 4; ++u) bb[u] = g_bbox[base0 + u*32 + lane];
        int cnt = 0;
        #pragma unroll
        for (int u = 0; u < 4; ++u) {
            bool hit = (bb[u].z > 0.0f) &&
                       (bb[u].x - bb[u].z <= bx1) && (bb[u].x + bb[u].z >= bx0) &&
                       (bb[u].y - bb[u].w <= by1) && (bb[u].y + bb[u].w >= by0);
            mk[u] = __ballot_sync(0xffffffffu, hit);
            cnt += __popc(mk[u]);
        }
        if (lane == 0) wcnt[h][wl] = cnt;
        __syncthreads();
        if (tid < 2) {
            int acc = 0;
            #pragma unroll
            for (int w2 = 0; w2 < 16; ++w2) { int t = wcnt[tid][w2]; wcnt[tid][w2] = acc; acc += t; }
            wcnt[tid][16] = acc;
        }
        __syncthreads();
        int off = wcnt[h][wl];
        #pragma unroll
        for (int u = 0; u < 4; ++u) {
            if ((mk[u] >> lane) & 1u) {
                int rank = __popc(mk[u] & ((1u << lane) - 1u));
                int gi = base0 + u*32 + lane;
                int pos = off + rank;
                sidx[h*NG + pos] = gi;
                sdep[h*NG + pos] = g_depth[gi];
            }
            off += __popc(mk[u]);
        }
        __syncthreads();
    }

    // ---------------- Phase 3: local rank sort per tile (512 thr each) -------
    {
        int h = tid >> 9;
        int tl = tid & 511;
        int n = wcnt[h][16];
        const float* dep = sdep + h*NG;
        for (int e = tl; e < n; e += 512) {
            float de = dep[e];
            int r = 0;
            int j = 0;
            #pragma unroll 4
            for (; j + 4 <= n; j += 4) {
                float d0 = dep[j], d1 = dep[j+1], d2 = dep[j+2], d3 = dep[j+3];
                r += (d0 < de) || (d0 == de && (j+0) < e);
                r += (d1 < de) || (d1 == de && (j+1) < e);
                r += (d2 < de) || (d2 == de && (j+2) < e);
                r += (d3 < de) || (d3 == de && (j+3) < e);
            }
            for (; j < n; ++j) {
                float dj = dep[j];
                r += (dj < de) || (dj == de && j < e);
            }
            sord[h*NG + r] = sidx[h*NG + e];
        }
        __syncthreads();
    }

    // ---------------- Phase 4: composite — 16 groups, no inner barriers ------
    const int grp = tid >> 6;          // 0..15
    const int h   = grp >> 3;          // tile half
    const int seg = grp & 7;
    const int pix = tid & 63;
    const int tile = tileBase + h;
    const int tx0 = (tile & 15) * 8;
    const int ty0 = (tile >> 4) * 8;
    const float px = (float)(tx0 + (pix & 7)) + 0.5f;
    const float py = (float)(ty0 + (pix >> 3)) + 0.5f;

    int n = wcnt[h][16];
    int slen = (n + 7) >> 3;
    int s0 = seg * slen;
    int s1 = min(s0 + slen, n);

    float T = 1.0f;
    float cr = 0.0f, cg = 0.0f, cb = 0.0f;

    const int* lst = sord + h*NG;
    if (s0 < s1) {
        int gi = lst[s0];
        float4 A = __ldg(&g_packed4[gi*3]);
        float4 B = __ldg(&g_packed4[gi*3 + 1]);
        float bc = __ldg((const float*)g_packed4 + gi*12 + 8);
        for (int j = s0; j < s1; ++j) {
            float4 An, Bn; float bcn = 0.0f;
            if (j + 1 < s1) {
                int gin = lst[j+1];
                An = __ldg(&g_packed4[gin*3]);
                Bn = __ldg(&g_packed4[gin*3 + 1]);
                bcn = __ldg((const float*)g_packed4 + gin*12 + 8);
            } else { An = A; Bn = B; }

            float dx = px - A.x;
            float dy = py - A.y;
            float power = -0.5f * (A.z*dx*dx + B.x*dy*dy) - A.w*dx*dy;
            float g = fminf(B.y * __expf(power), 0.99f);
            bool ok = (power <= 0.0f) && (g >= (1.0f/255.0f));
            float gg = ok ? g : 0.0f;
            float w = T * gg;
            cr = fmaf(w, B.z, cr);
            cg = fmaf(w, B.w, cg);
            cb = fmaf(w, bc, cb);
            T *= (1.0f - gg);

            A = An; B = Bn; bc = bcn;

            if (((j - s0) & 7) == 7 &&
                __all_sync(0xffffffffu, T < 1e-6f)) break;
        }
    }

    part[grp*64 + pix] = make_float4(cr, cg, cb, T);
    __syncthreads();

    if (tid < 128) {
        int hh = tid >> 6;             // tile half
        int p2 = tid & 63;
        float4 acc = part[(hh*8 + 0)*64 + p2];
        #pragma unroll
        for (int s2 = 1; s2 < 8; ++s2) {
            float4 q = part[(hh*8 + s2)*64 + p2];
            acc.x = fmaf(acc.w, q.x, acc.x);
            acc.y = fmaf(acc.w, q.y, acc.y);
            acc.z = fmaf(acc.w, q.z, acc.z);
            acc.w *= q.w;
        }
        int tl = tileBase + hh;
        int x = (tl & 15) * 8 + (p2 & 7);
        int y = (tl >> 4) * 8 + (p2 >> 3);
        out[0*(IMW*IMH) + y*IMW + x] = acc.x;
        out[1*(IMW*IMH) + y*IMW + x] = acc.y;
        out[2*(IMW*IMH) + y*IMW + x] = acc.z;
    }
}

extern "C" void kernel_launch(void* const* d_in, const int* in_sizes, int n_in,
                              void* d_out, int out_size)
{
    const float* pws        = (const float*)d_in[0];
    const float* shs        = (const float*)d_in[1];
    const float* alphas_raw = (const float*)d_in[2];
    const float* scales_raw = (const float*)d_in[3];
    const float* rots_raw   = (const float*)d_in[4];
    // d_in[5] = us (unused by the reference)
    const float* Rcw        = (const float*)d_in[6];
    const float* tcw        = (const float*)d_in[7];

    float* out = (float*)d_out;

    cudaFuncSetAttribute(fused_kernel,
                         cudaFuncAttributeMaxDynamicSharedMemorySize, SMEM_DYN);
    fused_kernel<<<NBLOCKS, NTHREADS, SMEM_DYN>>>(pws, shs, alphas_raw, scales_raw,
                                                  rots_raw, Rcw, tcw, out);
}